// round 14
// baseline (speedup 1.0000x reference)
#include <cuda_runtime.h>
#include <cuda_bf16.h>
#include <cuda_fp16.h>
#include <math.h>
#include <stdint.h>

#define NN 20000
#define EE 320000
#define HH 256
#define LL 6
#define GB 20
#define PG 1000
#define NPAD 20096   // 157*128

// ---------------- scratch ----------------------------------------------------
__device__ __half g_R16[(size_t)EE * HH];        // fp16 edge features (dst-sorted rows)
__device__ __half g_W16[LL * HH * HH];           // fp16 folded edge weights [l][n][k]
__device__ float g_bl[LL * HH];
__device__ float g_h[NN * HH];
__device__ float g_z[NPAD * HH];                 // fp32 accumulation target (pad rows stay 0)
__device__ float g_hn[NN * HH];
__device__ __nv_bfloat16 g_zhi[NPAD * HH];       // bf16 of final h (for scores)
__device__ __half g_t16[NPAD * HH];              // fp16 intermediate t
__device__ __half g_cw1_16[LL * HH * HH];        // fp16 node weights [l][n][k]
__device__ __half g_cw2_16[LL * HH * HH];
__device__ __nv_bfloat16 g_pahi[HH * HH], g_palo[HH * HH];  // paw1^T split (scores)
__device__ float g_scores[NN];
__device__ float g_attn[NN];
__device__ float g_stats[2];
__device__ float g_pooled[GB * HH];
// dst-sort structures (rebuilt every launch)
__device__ int g_cnt[NN];
__device__ int g_pos[EE];
__device__ int g_srcs[EE];
__device__ int g_dsts[EE];

__device__ __forceinline__ float siluf(float x) { return x / (1.f + expf(-x)); }

__device__ __forceinline__ uint32_t smem_u32(const void* p) {
    uint32_t a;
    asm("{ .reg .u64 t; cvta.to.shared.u64 t, %1; cvt.u32.u64 %0, t; }" : "=r"(a) : "l"(p));
    return a;
}
__device__ __forceinline__ uint32_t swz(uint32_t o)   { return o ^ ((o >> 3) & 0x70); }
__device__ __forceinline__ uint32_t swz64(uint32_t o) { return o ^ ((o >> 3) & 0x30); }

#define LDSM4(r, addr) \
    asm volatile("ldmatrix.sync.aligned.m8n8.x4.shared.b16 {%0,%1,%2,%3}, [%4];" \
        : "=r"((r)[0]), "=r"((r)[1]), "=r"((r)[2]), "=r"((r)[3]) : "r"(addr))

__device__ __forceinline__ void mma_bf16(float* d, const uint32_t* a, uint32_t b0, uint32_t b1) {
    asm volatile("mma.sync.aligned.m16n8k16.row.col.f32.bf16.bf16.f32 "
        "{%0,%1,%2,%3}, {%4,%5,%6,%7}, {%8,%9}, {%0,%1,%2,%3};"
        : "+f"(d[0]), "+f"(d[1]), "+f"(d[2]), "+f"(d[3])
        : "r"(a[0]), "r"(a[1]), "r"(a[2]), "r"(a[3]), "r"(b0), "r"(b1));
}
__device__ __forceinline__ void mma_f16(float* d, const uint32_t* a, uint32_t b0, uint32_t b1) {
    asm volatile("mma.sync.aligned.m16n8k16.row.col.f32.f16.f16.f32 "
        "{%0,%1,%2,%3}, {%4,%5,%6,%7}, {%8,%9}, {%0,%1,%2,%3};"
        : "+f"(d[0]), "+f"(d[1]), "+f"(d[2]), "+f"(d[3])
        : "r"(a[0]), "r"(a[1]), "r"(a[2]), "r"(a[3]), "r"(b0), "r"(b1));
}

#define CPA16(d, s) asm volatile("cp.async.cg.shared.global [%0], [%1], 16;" :: "r"(d), "l"(s) : "memory")
#define CPC        asm volatile("cp.async.commit_group;" ::: "memory")
#define CPW1       asm volatile("cp.async.wait_group 1;" ::: "memory")
#define CPW0       asm volatile("cp.async.wait_group 0;" ::: "memory")

#define RED4(p, v) asm volatile("red.global.add.v4.f32 [%0], {%1,%2,%3,%4};" \
    :: "l"(p), "f"((v).x), "f"((v).y), "f"((v).z), "f"((v).w) : "memory")

#define PIPE_SMEM (98304 + 1024)
#define NODE0_SMEM (2 * 32768 + 512)
#define MSG_STRIDE 136   // floats per msg row: 128 + 8 pad

// ---------------- dst counting sort (edge_index constant across layers) ------
__global__ void zero_init(const float* __restrict__ pab2) {
    int i = blockIdx.x * 256 + threadIdx.x;
    if (i < NN) { g_cnt[i] = 0; g_scores[i] = pab2[0]; }
}
__global__ void hist_kernel(const int* __restrict__ eidx) {
    int i = blockIdx.x * 256 + threadIdx.x;
    atomicAdd(&g_cnt[eidx[EE + i]], 1);
}
__global__ void scan_kernel() {
    __shared__ int sums[1024];
    int t = threadIdx.x;
    int base = t * 20;
    int local[20];
    int s = 0;
#pragma unroll
    for (int i = 0; i < 20; i++) {
        int b = base + i;
        int v = (b < NN) ? g_cnt[b] : 0;
        local[i] = s;
        s += v;
    }
    sums[t] = s;
    __syncthreads();
    for (int o = 1; o < 1024; o <<= 1) {
        int v = (t >= o) ? sums[t - o] : 0;
        __syncthreads();
        sums[t] += v;
        __syncthreads();
    }
    int excl = (t == 0) ? 0 : sums[t - 1];
#pragma unroll
    for (int i = 0; i < 20; i++) {
        int b = base + i;
        if (b < NN) g_cnt[b] = excl + local[i];
    }
}
__global__ void scatter_kernel(const int* __restrict__ eidx) {
    int i = blockIdx.x * 256 + threadIdx.x;
    int d = eidx[EE + i];
    int p = atomicAdd(&g_cnt[d], 1);
    g_pos[i] = p;
    g_srcs[p] = eidx[i];
    g_dsts[p] = d;
}

// ---------------- weight folding: W16_l = (ew2 @ lin_w[l])^T fp16 -----------
__global__ void prep_W(const float* __restrict__ ew2, const float* __restrict__ lin_w) {
    int l = blockIdx.x >> 8;
    int i = blockIdx.x & 255;   // K index
    int j = threadIdx.x;        // N index
    __shared__ float er[256];
    er[j] = ew2[i * 256 + j];
    __syncthreads();
    const float* lw = lin_w + l * 65536;
    float acc = 0.f;
#pragma unroll 8
    for (int m = 0; m < 256; m++) acc += er[m] * lw[m * 256 + j];
    g_W16[l * 65536 + j * 256 + i] = __float2half(acc);
}

__global__ void prep_bl(const float* __restrict__ eb2, const float* __restrict__ lin_w,
                        const float* __restrict__ lin_b) {
    int l = blockIdx.x;
    int j = threadIdx.x;
    const float* lw = lin_w + l * 65536;
    float acc = lin_b[l * 256 + j];
#pragma unroll 8
    for (int m = 0; m < 256; m++) acc += eb2[m] * lw[m * 256 + j];
    g_bl[l * 256 + j] = acc;
}

// ---------------- node weight transpose -> fp16 (tiled, coalesced) ----------
__global__ void prep_nw(const float* __restrict__ cw1, const float* __restrict__ cw2) {
    __shared__ float tile[32][33];
    int l = blockIdx.z >> 1, m = blockIdx.z & 1;
    const float* src = (m ? cw2 : cw1) + (size_t)l * 65536;
    __half* dst = (m ? g_cw2_16 : g_cw1_16) + (size_t)l * 65536;
    int n0 = blockIdx.x * 32, k0 = blockIdx.y * 32;
    int tx = threadIdx.x & 31, ty = threadIdx.x >> 5;   // 256 threads = 32x8
#pragma unroll
    for (int i = 0; i < 32; i += 8)
        tile[ty + i][tx] = src[(size_t)(k0 + ty + i) * 256 + n0 + tx];
    __syncthreads();
#pragma unroll
    for (int i = 0; i < 32; i += 8)
        dst[(size_t)(n0 + ty + i) * 256 + k0 + tx] = __float2half(tile[tx][ty + i]);
}

// ---------------- pool-attn weight transpose + bf16 split (tiled) -----------
__global__ void prep_pw(const float* __restrict__ paw1) {
    __shared__ float tile[32][33];
    int n0 = blockIdx.x * 32, k0 = blockIdx.y * 32;
    int tx = threadIdx.x & 31, ty = threadIdx.x >> 5;
#pragma unroll
    for (int i = 0; i < 32; i += 8)
        tile[ty + i][tx] = paw1[(size_t)(k0 + ty + i) * 256 + n0 + tx];
    __syncthreads();
#pragma unroll
    for (int i = 0; i < 32; i += 8) {
        float v = tile[tx][ty + i];
        __nv_bfloat16 hi = __float2bfloat16(v);
        size_t di = (size_t)(n0 + ty + i) * 256 + k0 + tx;
        g_pahi[di] = hi;
        g_palo[di] = __float2bfloat16(v - __bfloat162float(hi));
    }
}

// ---------------- r = relu(edge_attr @ ew1 + eb1) -> fp16 at sorted rows -----
__global__ void r_kernel(const float* __restrict__ ea, const float* __restrict__ ew1,
                         const float* __restrict__ eb1) {
    int e0 = blockIdx.x * 32;
    int j = threadIdx.x;            // 0..127 -> cols 2j, 2j+1
    __shared__ float eas[256];
    __shared__ int spos[32];
    eas[j] = ea[e0 * 8 + j];
    eas[j + 128] = ea[e0 * 8 + 128 + j];
    if (j < 32) spos[j] = g_pos[e0 + j];
    float w0[8], w1[8];
#pragma unroll
    for (int k = 0; k < 8; k++) {
        w0[k] = ew1[k * 256 + 2 * j];
        w1[k] = ew1[k * 256 + 2 * j + 1];
    }
    float b0 = eb1[2 * j], b1 = eb1[2 * j + 1];
    __syncthreads();
    __half2* out = (__half2*)g_R16;
    for (int e = 0; e < 32; e++) {
        float a0 = b0, a1 = b1;
#pragma unroll
        for (int k = 0; k < 8; k++) {
            float v = eas[e * 8 + k];
            a0 += v * w0[k];
            a1 += v * w1[k];
        }
        out[(size_t)spos[e] * 128 + j] =
            __floats2half2_rn(fmaxf(a0, 0.f), fmaxf(a1, 0.f));
    }
}

// ---------------- h = silu([x|c] @ in_w + in_b); also z = h ------------------
__global__ void input_proj(const float* __restrict__ x, const float* __restrict__ c,
                           const int* __restrict__ gid, const int* __restrict__ lid,
                           const float* __restrict__ inw, const float* __restrict__ inb) {
    int n0 = blockIdx.x * 8;
    int j = threadIdx.x;
    __shared__ float xs[8 * 16];
    __shared__ float cs[8];
    if (j < 128) xs[j] = x[n0 * 16 + j];
    if (j < 8) { int n = n0 + j; cs[j] = c[gid[n] * PG + lid[n]]; }
    float w[17];
#pragma unroll
    for (int k = 0; k < 17; k++) w[k] = inw[k * 256 + j];
    float b = inb[j];
    __syncthreads();
    for (int n = 0; n < 8; n++) {
        float acc = b + cs[n] * w[16];
#pragma unroll
        for (int k = 0; k < 16; k++) acc += xs[n * 16 + k] * w[k];
        float v = siluf(acc);
        g_h[(n0 + n) * 256 + j] = v;
        g_z[(n0 + n) * 256 + j] = v;
    }
}

// ---------------- edge GEMM (fp16) + run-length scatter (dst-sorted) --------
__global__ void __launch_bounds__(256, 2) edge_mma(int l) {
    extern __shared__ char sm[];
    uint32_t sbase = smem_u32(sm);
    float* sBias = (float*)(sm + 98304);
    int* sDst = (int*)(sm + 98304 + 512);

    int tid = threadIdx.x, lane = tid & 31, wid = tid >> 5;
    int wm = wid & 3, wn = wid >> 2;
    int col0 = blockIdx.x * 128, row0 = blockIdx.y * 128;

    if (tid < 128) sBias[tid] = g_bl[l * 256 + col0 + tid];
    if (tid >= 128) sDst[tid - 128] = g_dsts[row0 + tid - 128];

    const uint4* Ag = (const uint4*)g_R16 + (size_t)row0 * 32;
    const uint4* Bg = (const uint4*)g_W16 + (size_t)l * 8192 + (size_t)col0 * 32;

    float acc[16][4];
#pragma unroll
    for (int i = 0; i < 16; i++) { acc[i][0] = 0.f; acc[i][1] = 0.f; acc[i][2] = 0.f; acc[i][3] = 0.f; }

    auto issue = [&](int c, int s) {
        uint32_t sa = sbase + s * 32768;
#pragma unroll
        for (int i = 0; i < 4; i++) {
            int elem = tid + 256 * i;
            int r = elem >> 3, u = elem & 7;
            uint32_t o = swz((uint32_t)(r * 128 + u * 16));
            CPA16(sa + o,         Ag + (size_t)r * 32 + c * 8 + u);
            CPA16(sa + 16384 + o, Bg + (size_t)r * 32 + c * 8 + u);
        }
    };

    issue(0, 0); CPC;
    issue(1, 1); CPC;

#pragma unroll
    for (int c = 0; c < 4; c++) {
        int s = (c < 3) ? c : 0;
        if (c < 3) { CPW1; } else { CPW0; }
        __syncthreads();
        uint32_t sa = sbase + s * 32768;
#pragma unroll
        for (int ks = 0; ks < 4; ks++) {
            uint32_t a0[4], a1[4];
            int kb = ks * 32 + ((lane >> 4) << 4);
            LDSM4(a0, sa + swz((uint32_t)((wm * 32 + (lane & 15)) * 128 + kb)));
            LDSM4(a1, sa + swz((uint32_t)((wm * 32 + 16 + (lane & 15)) * 128 + kb)));
#pragma unroll
            for (int np = 0; np < 4; np++) {
                int g = lane >> 3, li = lane & 7;
                int brow = wn * 64 + np * 16 + ((g >> 1) << 3) + li;
                int bkb = ks * 32 + ((g & 1) << 4);
                uint32_t bh[4];
                LDSM4(bh, sa + 16384 + swz((uint32_t)(brow * 128 + bkb)));
#pragma unroll
                for (int t = 0; t < 2; t++) {
                    mma_f16(acc[0 * 8 + np * 2 + t], a0, bh[2 * t], bh[2 * t + 1]);
                    mma_f16(acc[1 * 8 + np * 2 + t], a1, bh[2 * t], bh[2 * t + 1]);
                }
            }
        }
        if (c < 2) { issue(c + 2, c + 2 == 2 ? 2 : 0); CPC; }
    }

    // ---- stage messages in smem ----
    __syncthreads();
    float* msg = (float*)sm;     // [128][MSG_STRIDE] fp32

    int q = lane >> 2;
    int c2 = (lane & 3) * 2;
    int src_[2][2];
#pragma unroll
    for (int mt = 0; mt < 2; mt++)
#pragma unroll
        for (int h = 0; h < 2; h++)
            src_[mt][h] = g_srcs[row0 + wm * 32 + mt * 16 + h * 8 + q];

#pragma unroll
    for (int mt = 0; mt < 2; mt++) {
#pragma unroll
        for (int nt = 0; nt < 8; nt++) {
            float* a = acc[mt * 8 + nt];
            int coln = wn * 64 + nt * 8 + c2;
            int col = col0 + coln;
            float2 bb = *(float2*)(sBias + coln);
#pragma unroll
            for (int h = 0; h < 2; h++) {
                const float2 hv = *(const float2*)(g_h + (size_t)src_[mt][h] * 256 + col);
                float v0 = fmaxf(a[2 * h + 0] + bb.x + hv.x, 0.f);
                float v1 = fmaxf(a[2 * h + 1] + bb.y + hv.y, 0.f);
                int rowloc = wm * 32 + mt * 16 + h * 8 + q;
                *(float2*)(msg + rowloc * MSG_STRIDE + coln) = make_float2(v0, v1);
            }
        }
    }
    __syncthreads();

    // ---- run-length accumulate down sorted-dst rows; one red per run ----
    int cg = tid & 31;
    int seg = tid >> 5;
    int r0g = seg * 16;
    float* zcol = g_z + col0 + cg * 4;
    float4 a4 = *(const float4*)(msg + r0g * MSG_STRIDE + cg * 4);
    int cur = sDst[r0g];
#pragma unroll
    for (int r = 1; r < 16; r++) {
        int d = sDst[r0g + r];
        float4 v = *(const float4*)(msg + (r0g + r) * MSG_STRIDE + cg * 4);
        if (d == cur) {
            a4.x += v.x; a4.y += v.y; a4.z += v.z; a4.w += v.w;
        } else {
            RED4(zcol + (size_t)cur * 256, a4);
            cur = d;
            a4 = v;
        }
    }
    RED4(zcol + (size_t)cur * 256, a4);
}

// ---------------- node0: fp32 z LDG->fp16 convert GEMM (k-chunk 64) ----------
// Stage: A 16KB @0, B 16KB @16384; stride 32768; 2 stages; 4 chunks.
__global__ void __launch_bounds__(256, 2) node0_mma(int l, const float* __restrict__ cb1) {
    extern __shared__ char sm[];
    uint32_t sbase = smem_u32(sm);
    float* sBias = (float*)(sm + 2 * 32768);

    int tid = threadIdx.x, lane = tid & 31, wid = tid >> 5;
    int wm = wid & 3, wn = wid >> 2;
    int col0 = blockIdx.x * 128, row0 = blockIdx.y * 128;

    if (tid < 128) sBias[tid] = cb1[l * 256 + col0 + tid];

    const float* Az = g_z + (size_t)row0 * 256;
    const uint4* B4 = (const uint4*)(g_cw1_16 + (size_t)l * 65536) + (size_t)col0 * 32;

    float acc[16][4];
#pragma unroll
    for (int i = 0; i < 16; i++) { acc[i][0] = 0.f; acc[i][1] = 0.f; acc[i][2] = 0.f; acc[i][3] = 0.f; }

    float4 pa[4][2];   // [i][half]: 8 floats per (r,u) slot, 4 slots/thread

    auto ldgA = [&](int c) {
#pragma unroll
        for (int i = 0; i < 4; i++) {
            int elem = tid + 256 * i;
            int r = elem >> 3, u = elem & 7;
            const float* src = Az + (size_t)r * 256 + c * 64 + u * 8;
            pa[i][0] = *(const float4*)src;
            pa[i][1] = *(const float4*)(src + 4);
        }
    };
    auto stsA = [&](int s) {
#pragma unroll
        for (int i = 0; i < 4; i++) {
            int elem = tid + 256 * i;
            int r = elem >> 3, u = elem & 7;
            __half2 b0 = __floats2half2_rn(pa[i][0].x, pa[i][0].y);
            __half2 b1 = __floats2half2_rn(pa[i][0].z, pa[i][0].w);
            __half2 b2 = __floats2half2_rn(pa[i][1].x, pa[i][1].y);
            __half2 b3 = __floats2half2_rn(pa[i][1].z, pa[i][1].w);
            uint4 val;
            val.x = *(uint32_t*)&b0; val.y = *(uint32_t*)&b1;
            val.z = *(uint32_t*)&b2; val.w = *(uint32_t*)&b3;
            *(uint4*)(sm + s * 32768 + swz((uint32_t)(r * 128 + u * 16))) = val;
        }
    };
    auto issueB = [&](int c, int s) {
        uint32_t sa = sbase + s * 32768 + 16384;
#pragma unroll
        for (int i = 0; i < 4; i++) {
            int elem = tid + 256 * i;
            int r = elem >> 3, u = elem & 7;
            CPA16(sa + swz((uint32_t)(r * 128 + u * 16)), B4 + (size_t)r * 32 + c * 8 + u);
        }
    };

    ldgA(0);
    issueB(0, 0); CPC;
    issueB(1, 1); CPC;
    stsA(0);
    ldgA(1);
    CPW1;
    __syncthreads();

#pragma unroll 1
    for (int c = 0; c < 4; c++) {
        uint32_t sa = sbase + (c & 1) * 32768;
#pragma unroll
        for (int ks = 0; ks < 4; ks++) {
            uint32_t a0[4], a1[4];
            int kb = ks * 32 + ((lane >> 4) << 4);
            LDSM4(a0, sa + swz((uint32_t)((wm * 32 + (lane & 15)) * 128 + kb)));
            LDSM4(a1, sa + swz((uint32_t)((wm * 32 + 16 + (lane & 15)) * 128 + kb)));
#pragma unroll
            for (int np = 0; np < 4; np++) {
                int g = lane >> 3, li = lane & 7;
                int brow = wn * 64 + np * 16 + ((g >> 1) << 3) + li;
                int bkb = ks * 32 + ((g & 1) << 4);
                uint32_t bh[4];
                LDSM4(bh, sa + 16384 + swz((uint32_t)(brow * 128 + bkb)));
#pragma unroll
                for (int t = 0; t < 2; t++) {
                    mma_f16(acc[0 * 8 + np * 2 + t], a0, bh[2 * t], bh[2 * t + 1]);
                    mma_f16(acc[1 * 8 + np * 2 + t], a1, bh[2 * t], bh[2 * t + 1]);
                }
            }
        }
        if (c < 3) {
            __syncthreads();                 // readers done with stage (c+1)&1
            stsA((c + 1) & 1);
            if (c < 2) { ldgA(c + 2); issueB(c + 2, c & 1); CPC; CPW1; }
            else       { CPW0; }
            __syncthreads();
        }
    }

    int q = lane >> 2;
    int c2 = (lane & 3) * 2;
#pragma unroll
    for (int mt = 0; mt < 2; mt++) {
#pragma unroll
        for (int nt = 0; nt < 8; nt++) {
            float* a = acc[mt * 8 + nt];
            int coln = wn * 64 + nt * 8 + c2;
            int col = col0 + coln;
            float2 bb = *(float2*)(sBias + coln);
#pragma unroll
            for (int h = 0; h < 2; h++) {
                int rr = row0 + wm * 32 + mt * 16 + h * 8 + q;
                float v0 = siluf(a[2 * h + 0] + bb.x);
                float v1 = siluf(a[2 * h + 1] + bb.y);
                *(__half2*)(g_t16 + (size_t)rr * 256 + col) = __floats2half2_rn(v0, v1);
            }
        }
    }
}

// ---------------- node1: t16 @ cw2 (fp16 single) -> g_hn (fp32) --------------
__global__ void __launch_bounds__(256, 2) node1_mma(int l, const float* __restrict__ cb2) {
    extern __shared__ char sm[];
    uint32_t sbase = smem_u32(sm);
    float* sBias = (float*)(sm + 98304);

    int tid = threadIdx.x, lane = tid & 31, wid = tid >> 5;
    int wm = wid & 3, wn = wid >> 2;
    int col0 = blockIdx.x * 128, row0 = blockIdx.y * 128;

    if (tid < 128) sBias[tid] = cb2[l * 256 + col0 + tid];

    const uint4* Ag = (const uint4*)g_t16 + (size_t)row0 * 32;
    const uint4* Bg = (const uint4*)(g_cw2_16 + (size_t)l * 65536) + (size_t)col0 * 32;

    float acc[16][4];
#pragma unroll
    for (int i = 0; i < 16; i++) { acc[i][0] = 0.f; acc[i][1] = 0.f; acc[i][2] = 0.f; acc[i][3] = 0.f; }

    auto issue = [&](int c, int s) {
        uint32_t sa = sbase + s * 32768;
#pragma unroll
        for (int i = 0; i < 4; i++) {
            int elem = tid + 256 * i;
            int r = elem >> 3, u = elem & 7;
            uint32_t o = swz((uint32_t)(r * 128 + u * 16));
            CPA16(sa + o,         Ag + (size_t)r * 32 + c * 8 + u);
            CPA16(sa + 16384 + o, Bg + (size_t)r * 32 + c * 8 + u);
        }
    };

    issue(0, 0); CPC;
    issue(1, 1); CPC;

#pragma unroll
    for (int c = 0; c < 4; c++) {
        int s = (c < 3) ? c : 0;
        if (c < 3) { CPW1; } else { CPW0; }
        __syncthreads();
        uint32_t sa = sbase + s * 32768;
#pragma unroll
        for (int ks = 0; ks < 4; ks++) {
            uint32_t a0[4], a1[4];
            int kb = ks * 32 + ((lane >> 4) << 4);
            LDSM4(a0, sa + swz((uint32_t)((wm * 32 + (lane & 15)) * 128 + kb)));
            LDSM4(a1, sa + swz((uint32_t)((wm * 32 + 16 + (lane & 15)) * 128 + kb)));
#pragma unroll
            for (int np = 0; np < 4; np++) {
                int g = lane >> 3, li = lane & 7;
                int brow = wn * 64 + np * 16 + ((g >> 1) << 3) + li;
                int bkb = ks * 32 + ((g & 1) << 4);
                uint32_t bh[4];
                LDSM4(bh, sa + 16384 + swz((uint32_t)(brow * 128 + bkb)));
#pragma unroll
                for (int t = 0; t < 2; t++) {
                    mma_f16(acc[0 * 8 + np * 2 + t], a0, bh[2 * t], bh[2 * t + 1]);
                    mma_f16(acc[1 * 8 + np * 2 + t], a1, bh[2 * t], bh[2 * t + 1]);
                }
            }
        }
        if (c < 2) { issue(c + 2, c + 2 == 2 ? 2 : 0); CPC; }
    }

    int q = lane >> 2;
    int c2 = (lane & 3) * 2;
#pragma unroll
    for (int mt = 0; mt < 2; mt++) {
#pragma unroll
        for (int nt = 0; nt < 8; nt++) {
            float* a = acc[mt * 8 + nt];
            int coln = wn * 64 + nt * 8 + c2;
            int col = col0 + coln;
            float2 bb = *(float2*)(sBias + coln);
#pragma unroll
            for (int h = 0; h < 2; h++) {
                int rr = row0 + wm * 32 + mt * 16 + h * 8 + q;
                if (rr < NN)
                    *(float2*)(g_hn + (size_t)rr * 256 + col) =
                        make_float2(a[2 * h + 0] + bb.x, a[2 * h + 1] + bb.y);
            }
        }
    }
}

// ---------------- scores: zhi @ paw1 (bf16 2-term) -> tanh -> dot paw2 -------
__global__ void __launch_bounds__(256, 2) node_mma2(const float* __restrict__ pab1,
                                                    const float* __restrict__ w2) {
    extern __shared__ char sm[];
    uint32_t sbase = smem_u32(sm);
    float* sBias = (float*)(sm + 98304);
    float* sW2 = (float*)(sm + 98304 + 512);

    int tid = threadIdx.x, lane = tid & 31, wid = tid >> 5;
    int wm = wid & 3, wn = wid >> 2;
    int col0 = blockIdx.x * 128, row0 = blockIdx.y * 128;

    if (tid < 128) { sBias[tid] = pab1[col0 + tid]; sW2[tid] = w2[col0 + tid]; }

    const uint4* A4 = (const uint4*)g_zhi + (size_t)row0 * 32;
    const uint4* Bh4 = (const uint4*)g_pahi + (size_t)col0 * 32;
    const uint4* Bl4 = (const uint4*)g_palo + (size_t)col0 * 32;

    float acc[16][4];
#pragma unroll
    for (int i = 0; i < 16; i++) { acc[i][0] = 0.f; acc[i][1] = 0.f; acc[i][2] = 0.f; acc[i][3] = 0.f; }

    auto issue = [&](int c, int s) {
        uint32_t sa = sbase + s * 49152;
#pragma unroll
        for (int i = 0; i < 4; i++) {
            int elem = tid + 256 * i;
            int r = elem >> 3, u = elem & 7;
            uint32_t o = swz((uint32_t)(r * 128 + u * 16));
            CPA16(sa + o,         A4  + (size_t)r * 32 + c * 8 + u);
            CPA16(sa + 16384 + o, Bh4 + (size_t)r * 32 + c * 8 + u);
            CPA16(sa + 32768 + o, Bl4 + (size_t)r * 32 + c * 8 + u);
        }
    };

    issue(0, 0); CPC;
    issue(1, 1); CPC;

#pragma unroll
    for (int c = 0; c < 4; c++) {
        if (c < 3) { CPW1; } else { CPW0; }
        __syncthreads();
        uint32_t sa = sbase + (c & 1) * 49152;
#pragma unroll
        for (int ks = 0; ks < 4; ks++) {
            uint32_t a0[4], a1[4];
            int kb = ks * 32 + ((lane >> 4) << 4);
            LDSM4(a0, sa + swz((uint32_t)((wm * 32 + (lane & 15)) * 128 + kb)));
            LDSM4(a1, sa + swz((uint32_t)((wm * 32 + 16 + (lane & 15)) * 128 + kb)));
#pragma unroll
            for (int np = 0; np < 4; np++) {
                int g = lane >> 3, li = lane & 7;
                int brow = wn * 64 + np * 16 + ((g >> 1) << 3) + li;
                int bkb = ks * 32 + ((g & 1) << 4);
                uint32_t bh[4], bl[4];
                LDSM4(bh, sa + 16384 + swz((uint32_t)(brow * 128 + bkb)));
                LDSM4(bl, sa + 32768 + swz((uint32_t)(brow * 128 + bkb)));
#pragma unroll
                for (int t = 0; t < 2; t++) {
                    mma_bf16(acc[0 * 8 + np * 2 + t], a0, bh[2 * t], bh[2 * t + 1]);
                    mma_bf16(acc[0 * 8 + np * 2 + t], a0, bl[2 * t], bl[2 * t + 1]);
                    mma_bf16(acc[1 * 8 + np * 2 + t], a1, bh[2 * t], bh[2 * t + 1]);
                    mma_bf16(acc[1 * 8 + np * 2 + t], a1, bl[2 * t], bl[2 * t + 1]);
                }
            }
        }
        if (c < 2) { __syncthreads(); issue(c + 2, c & 1); CPC; }
    }

    int q = lane >> 2;
    int c2 = (lane & 3) * 2;
#pragma unroll
    for (int mt = 0; mt < 2; mt++) {
#pragma unroll
        for (int h = 0; h < 2; h++) {
            int rr = row0 + wm * 32 + mt * 16 + h * 8 + q;
            float part = 0.f;
#pragma unroll
            for (int nt = 0; nt < 8; nt++) {
                float* a = acc[mt * 8 + nt];
                int coln = wn * 64 + nt * 8 + c2;
                part += tanhf(a[2 * h + 0] + sBias[coln])     * sW2[coln];
                part += tanhf(a[2 * h + 1] + sBias[coln + 1]) * sW2[coln + 1];
            }
            part += __shfl_xor_sync(~0u, part, 1);
            part += __shfl_xor_sync(~0u, part, 2);
            if ((lane & 3) == 0 && rr < NN) atomicAdd(&g_scores[rr], part);
        }
    }
}

// ---------------- LayerNorm + residual silu update (float4) ------------------
__global__ void ln_update(int l, const float* __restrict__ lng, const float* __restrict__ lnb) {
    int warp = threadIdx.x >> 5, lane = threadIdx.x & 31;
    int n = blockIdx.x * 8 + warp;
    const float* g = lng + l * 256;
    const float* b = lnb + l * 256;
    const float4* row4 = (const float4*)(g_hn + (size_t)n * 256);
    float4 v[2];
    float s = 0.f, ss = 0.f;
#pragma unroll
    for (int t = 0; t < 2; t++) {
        v[t] = row4[lane + 32 * t];
        s += v[t].x + v[t].y + v[t].z + v[t].w;
        ss += v[t].x * v[t].x + v[t].y * v[t].y + v[t].z * v[t].z + v[t].w * v[t].w;
    }
#pragma unroll
    for (int o = 16; o > 0; o >>= 1) {
        s += __shfl_xor_sync(~0u, s, o);
        ss += __shfl_xor_sync(~0u, ss, o);
    }
    float m = s * (1.f / 256.f);
    float var = ss * (1.f / 256.f) - m * m;
    float r = rsqrtf(var + 1e-5f);
    float4* hrow = (float4*)(g_h + (size_t)n * 256);
    float4* zrow = (float4*)(g_z + (size_t)n * 256);
#pragma unroll
    for (int t = 0; t < 2; t++) {
        int ci = (lane + 32 * t) * 4;
        float4 hv = hrow[lane + 32 * t];
        float4 nh;
        nh.x = hv.x + siluf((v[t].x - m) * r * g[ci + 0] + b[ci + 0]);
        nh.y = hv.y + siluf((v[t].y - m) * r * g[ci + 1] + b[ci + 1]);
        nh.z = hv.z + siluf((v[t].z - m) * r * g[ci + 2] + b[ci + 2]);
        nh.w = hv.w + siluf((v[t].w - m) * r * g[ci + 3] + b[ci + 3]);
        hrow[lane + 32 * t] = nh;
        zrow[lane + 32 * t] = nh;
        if (l == LL - 1) {
            __nv_bfloat162* zh = (__nv_bfloat162*)(g_zhi + (size_t)n * 256);
            zh[(lane + 32 * t) * 2 + 0] = __nv_bfloat162(__float2bfloat16(nh.x), __float2bfloat16(nh.y));
            zh[(lane + 32 * t) * 2 + 1] = __nv_bfloat162(__float2bfloat16(nh.z), __float2bfloat16(nh.w));
        }
    }
}

// ---------------- global softmax stats --------------------------------------
__global__ void softmax_stats() {
    __shared__ float red[1024];
    int t = threadIdx.x;
    float m = -1e30f;
    for (int i = t; i < NN; i += 1024) m = fmaxf(m, g_scores[i]);
    red[t] = m;
    __syncthreads();
    for (int o = 512; o > 0; o >>= 1) {
        if (t < o) red[t] = fmaxf(red[t], red[t + o]);
        __syncthreads();
    }
    float gmax = red[0];
    __syncthreads();
    float s = 0.f;
    for (int i = t; i < NN; i += 1024) s += expf(g_scores[i] - gmax);
    red[t] = s;
    __syncthreads();
    for (int o = 512; o > 0; o >>= 1) {
        if (t < o) red[t] += red[t + o];
        __syncthreads();
    }
    if (t == 0) { g_stats[0] = gmax; g_stats[1] = red[0]; }
}

// ---------------- per-graph renormalized attention --------------------------
__global__ void seg_attn() {
    int g = blockIdx.x, t = threadIdx.x;
    float gmax = g_stats[0], Z = g_stats[1];
    int base = g * PG;
    float s = 0.f;
    for (int i = t; i < PG; i += 256) s += expf(g_scores[base + i] - gmax);
    __shared__ float red[256];
    red[t] = s;
    __syncthreads();
    for (int o = 128; o > 0; o >>= 1) {
        if (t < o) red[t] += red[t + o];
        __syncthreads();
    }
    float denom = red[0] / Z + 1e-8f;
    float scale = 1.f / (Z * denom);
    for (int i = t; i < PG; i += 256) g_attn[base + i] = expf(g_scores[base + i] - gmax) * scale;
    g_pooled[g * 256 + t] = 0.f;
}

// ---------------- weighted pooling ------------------------------------------
__global__ void pool_kernel() {
    int g = blockIdx.x, chunk = blockIdx.y, j = threadIdx.x;
    int base = g * PG + chunk * 50;
    float acc = 0.f;
    for (int i = 0; i < 50; i++)
        acc += g_h[(size_t)(base + i) * 256 + j] * g_attn[base + i];
    atomicAdd(&g_pooled[g * 256 + j], acc);
}

// ---------------- head -------------------------------------------------------
__global__ void head_kernel(const float* __restrict__ hw1, const float* __restrict__ hb1,
                            const float* __restrict__ hw2, const float* __restrict__ hb2,
                            float* __restrict__ out) {
    int g = blockIdx.x, j = threadIdx.x;
    __shared__ float ps[256];
    __shared__ float red[256];
    ps[j] = g_pooled[g * 256 + j];
    __syncthreads();
    float acc = hb1[j];
#pragma unroll 8
    for (int k = 0; k < 256; k++) acc += ps[k] * hw1[k * 256 + j];
    red[j] = siluf(acc) * hw2[j];
    __syncthreads();
    for (int o = 128; o > 0; o >>= 1) {
        if (j < o) red[j] += red[j + o];
        __syncthreads();
    }
    if (j == 0) out[g] = red[0] + hb2[0];
}

// ---------------- launch -----------------------------------------------------
extern "C" void kernel_launch(void* const* d_in, const int* in_sizes, int n_in,
                              void* d_out, int out_size) {
    const float* x    = (const float*)d_in[0];
    const float* ea   = (const float*)d_in[1];
    const float* c    = (const float*)d_in[2];
    const int*   eidx = (const int*)  d_in[3];
    const int*   gid  = (const int*)  d_in[4];
    const int*   lid  = (const int*)  d_in[5];
    const float* ew1  = (const float*)d_in[6];
    const float* eb1  = (const float*)d_in[7];
    const float* ew2  = (const float*)d_in[8];
    const float* eb2  = (const float*)d_in[9];
    const float* inw  = (const float*)d_in[10];
    const float* inb  = (const float*)d_in[11];
    const float* lin_w = (const float*)d_in[12];
    const float* lin_b = (const float*)d_in[13];
    const float* cw1  = (const float*)d_in[14];
    const float* cb1  = (const float*)d_in[15];
    const float* cw2  = (const float*)d_in[16];
    const float* cb2  = (const float*)d_in[17];
    const float* lng  = (const float*)d_in[18];
    const float* lnb  = (const float*)d_in[19];
    const float* paw1 = (const float*)d_in[20];
    const float* pab1 = (const float*)d_in[21];
    const float* paw2 = (const float*)d_in[22];
    const float* pab2 = (const float*)d_in[23];
    const float* hw1  = (const float*)d_in[24];
    const float* hb1  = (const float*)d_in[25];
    const float* hw2  = (const float*)d_in[26];
    const float* hb2  = (const float*)d_in[27];
    float* out = (float*)d_out;

    static int attr_done = 0;
    if (!attr_done) {
        cudaFuncSetAttribute((const void*)edge_mma,
                             cudaFuncAttributeMaxDynamicSharedMemorySize, PIPE_SMEM);
        cudaFuncSetAttribute((const void*)node0_mma,
                             cudaFuncAttributeMaxDynamicSharedMemorySize, NODE0_SMEM);
        cudaFuncSetAttribute((const void*)node1_mma,
                             cudaFuncAttributeMaxDynamicSharedMemorySize, PIPE_SMEM);
        cudaFuncSetAttribute((const void*)node_mma2,
                             cudaFuncAttributeMaxDynamicSharedMemorySize, PIPE_SMEM);
        attr_done = 1;
    }

    // dst counting sort (edge_index constant across layers; rebuilt per launch)
    zero_init<<<(NN + 255) / 256, 256>>>(pab2);
    hist_kernel<<<EE / 256, 256>>>(eidx);
    scan_kernel<<<1, 1024>>>();
    scatter_kernel<<<EE / 256, 256>>>(eidx);

    prep_W<<<LL * 256, 256>>>(ew2, lin_w);
    prep_bl<<<LL, 256>>>(eb2, lin_w, lin_b);
    prep_nw<<<dim3(8, 8, LL * 2), 256>>>(cw1, cw2);
    prep_pw<<<dim3(8, 8), 256>>>(paw1);
    r_kernel<<<EE / 32, 128>>>(ea, ew1, eb1);
    input_proj<<<NN / 8, 256>>>(x, c, gid, lid, inw, inb);

    for (int l = 0; l < LL; l++) {
        edge_mma<<<dim3(2, EE / 128), 256, PIPE_SMEM>>>(l);
        node0_mma<<<dim3(2, NPAD / 128), 256, NODE0_SMEM>>>(l, cb1);
        node1_mma<<<dim3(2, NPAD / 128), 256, PIPE_SMEM>>>(l, cb2);
        ln_update<<<NN / 8, 256>>>(l, lng, lnb);
    }

    node_mma2<<<dim3(2, NPAD / 128), 256, PIPE_SMEM>>>(pab1, paw2);
    softmax_stats<<<1, 1024>>>();
    seg_attn<<<GB, 256>>>();
    pool_kernel<<<dim3(GB, PG / 50), 256>>>();
    head_kernel<<<GB, 256>>>(hw1, hb1, hw2, hb2, out);
    (void)in_sizes; (void)n_in; (void)out_size;
}

// round 15
// speedup vs baseline: 1.0227x; 1.0227x over previous
#include <cuda_runtime.h>
#include <cuda_bf16.h>
#include <cuda_fp16.h>
#include <math.h>
#include <stdint.h>

#define NN 20000
#define EE 320000
#define HH 256
#define LL 6
#define GB 20
#define PG 1000
#define NPAD 20096   // 157*128

// ---------------- scratch ----------------------------------------------------
__device__ __half g_R16[(size_t)EE * HH];        // fp16 edge features (dst-sorted rows)
__device__ __half g_W16[LL * HH * HH];           // fp16 folded edge weights [l][n][k]
__device__ float g_bl[LL * HH];
__device__ float g_h[NN * HH];
__device__ float g_z[NPAD * HH];                 // fp32 accumulation target (pad rows stay 0)
__device__ float g_hn[NN * HH];
__device__ __nv_bfloat16 g_zhi[NPAD * HH];       // bf16 of final h (for scores)
__device__ __half g_t16[NPAD * HH];              // fp16 intermediate t
__device__ __half g_cw1_16[LL * HH * HH];        // fp16 node weights [l][n][k]
__device__ __half g_cw2_16[LL * HH * HH];
__device__ __nv_bfloat16 g_pahi[HH * HH], g_palo[HH * HH];  // paw1^T split (scores)
__device__ float g_scores[NN];
__device__ float g_attn[NN];
__device__ float g_stats[2];
__device__ float g_pooled[GB * HH];
// dst-sort structures (rebuilt every launch)
__device__ int g_cnt[NN];
__device__ int g_pos[EE];
__device__ int g_srcs[EE];
__device__ int g_dsts[EE];

__device__ __forceinline__ float siluf(float x) { return x / (1.f + expf(-x)); }

__device__ __forceinline__ uint32_t smem_u32(const void* p) {
    uint32_t a;
    asm("{ .reg .u64 t; cvta.to.shared.u64 t, %1; cvt.u32.u64 %0, t; }" : "=r"(a) : "l"(p));
    return a;
}
__device__ __forceinline__ uint32_t swz(uint32_t o)   { return o ^ ((o >> 3) & 0x70); }
__device__ __forceinline__ uint32_t swz64(uint32_t o) { return o ^ ((o >> 3) & 0x30); }

#define LDSM4(r, addr) \
    asm volatile("ldmatrix.sync.aligned.m8n8.x4.shared.b16 {%0,%1,%2,%3}, [%4];" \
        : "=r"((r)[0]), "=r"((r)[1]), "=r"((r)[2]), "=r"((r)[3]) : "r"(addr))

__device__ __forceinline__ void mma_bf16(float* d, const uint32_t* a, uint32_t b0, uint32_t b1) {
    asm volatile("mma.sync.aligned.m16n8k16.row.col.f32.bf16.bf16.f32 "
        "{%0,%1,%2,%3}, {%4,%5,%6,%7}, {%8,%9}, {%0,%1,%2,%3};"
        : "+f"(d[0]), "+f"(d[1]), "+f"(d[2]), "+f"(d[3])
        : "r"(a[0]), "r"(a[1]), "r"(a[2]), "r"(a[3]), "r"(b0), "r"(b1));
}
__device__ __forceinline__ void mma_f16(float* d, const uint32_t* a, uint32_t b0, uint32_t b1) {
    asm volatile("mma.sync.aligned.m16n8k16.row.col.f32.f16.f16.f32 "
        "{%0,%1,%2,%3}, {%4,%5,%6,%7}, {%8,%9}, {%0,%1,%2,%3};"
        : "+f"(d[0]), "+f"(d[1]), "+f"(d[2]), "+f"(d[3])
        : "r"(a[0]), "r"(a[1]), "r"(a[2]), "r"(a[3]), "r"(b0), "r"(b1));
}

#define CPA16(d, s) asm volatile("cp.async.cg.shared.global [%0], [%1], 16;" :: "r"(d), "l"(s) : "memory")
#define CPC        asm volatile("cp.async.commit_group;" ::: "memory")
#define CPW1       asm volatile("cp.async.wait_group 1;" ::: "memory")
#define CPW0       asm volatile("cp.async.wait_group 0;" ::: "memory")

#define RED4(p, v) asm volatile("red.global.add.v4.f32 [%0], {%1,%2,%3,%4};" \
    :: "l"(p), "f"((v).x), "f"((v).y), "f"((v).z), "f"((v).w) : "memory")

#define PIPE_SMEM (98304 + 1024)
#define NODE0_SMEM (2 * 16384 + 512)
#define MSG_STRIDE 136   // floats per msg row: 128 + 8 pad

// ---------------- dst counting sort (edge_index constant across layers) ------
__global__ void zero_init(const float* __restrict__ pab2) {
    int i = blockIdx.x * 256 + threadIdx.x;
    if (i < NN) { g_cnt[i] = 0; g_scores[i] = pab2[0]; }
}
__global__ void hist_kernel(const int* __restrict__ eidx) {
    int i = blockIdx.x * 256 + threadIdx.x;
    atomicAdd(&g_cnt[eidx[EE + i]], 1);
}
__global__ void scan_kernel() {
    __shared__ int sums[1024];
    int t = threadIdx.x;
    int base = t * 20;
    int local[20];
    int s = 0;
#pragma unroll
    for (int i = 0; i < 20; i++) {
        int b = base + i;
        int v = (b < NN) ? g_cnt[b] : 0;
        local[i] = s;
        s += v;
    }
    sums[t] = s;
    __syncthreads();
    for (int o = 1; o < 1024; o <<= 1) {
        int v = (t >= o) ? sums[t - o] : 0;
        __syncthreads();
        sums[t] += v;
        __syncthreads();
    }
    int excl = (t == 0) ? 0 : sums[t - 1];
#pragma unroll
    for (int i = 0; i < 20; i++) {
        int b = base + i;
        if (b < NN) g_cnt[b] = excl + local[i];
    }
}
__global__ void scatter_kernel(const int* __restrict__ eidx) {
    int i = blockIdx.x * 256 + threadIdx.x;
    int d = eidx[EE + i];
    int p = atomicAdd(&g_cnt[d], 1);
    g_pos[i] = p;
    g_srcs[p] = eidx[i];
    g_dsts[p] = d;
}

// ---------------- weight folding: W16_l = (ew2 @ lin_w[l])^T fp16 -----------
__global__ void prep_W(const float* __restrict__ ew2, const float* __restrict__ lin_w) {
    int l = blockIdx.x >> 8;
    int i = blockIdx.x & 255;   // K index
    int j = threadIdx.x;        // N index
    __shared__ float er[256];
    er[j] = ew2[i * 256 + j];
    __syncthreads();
    const float* lw = lin_w + l * 65536;
    float acc = 0.f;
#pragma unroll 8
    for (int m = 0; m < 256; m++) acc += er[m] * lw[m * 256 + j];
    g_W16[l * 65536 + j * 256 + i] = __float2half(acc);
}

__global__ void prep_bl(const float* __restrict__ eb2, const float* __restrict__ lin_w,
                        const float* __restrict__ lin_b) {
    int l = blockIdx.x;
    int j = threadIdx.x;
    const float* lw = lin_w + l * 65536;
    float acc = lin_b[l * 256 + j];
#pragma unroll 8
    for (int m = 0; m < 256; m++) acc += eb2[m] * lw[m * 256 + j];
    g_bl[l * 256 + j] = acc;
}

// ---------------- node weight transpose -> fp16 (tiled, coalesced) ----------
__global__ void prep_nw(const float* __restrict__ cw1, const float* __restrict__ cw2) {
    __shared__ float tile[32][33];
    int l = blockIdx.z >> 1, m = blockIdx.z & 1;
    const float* src = (m ? cw2 : cw1) + (size_t)l * 65536;
    __half* dst = (m ? g_cw2_16 : g_cw1_16) + (size_t)l * 65536;
    int n0 = blockIdx.x * 32, k0 = blockIdx.y * 32;
    int tx = threadIdx.x & 31, ty = threadIdx.x >> 5;   // 256 threads = 32x8
#pragma unroll
    for (int i = 0; i < 32; i += 8)
        tile[ty + i][tx] = src[(size_t)(k0 + ty + i) * 256 + n0 + tx];
    __syncthreads();
#pragma unroll
    for (int i = 0; i < 32; i += 8)
        dst[(size_t)(n0 + ty + i) * 256 + k0 + tx] = __float2half(tile[tx][ty + i]);
}

// ---------------- pool-attn weight transpose + bf16 split (tiled) -----------
__global__ void prep_pw(const float* __restrict__ paw1) {
    __shared__ float tile[32][33];
    int n0 = blockIdx.x * 32, k0 = blockIdx.y * 32;
    int tx = threadIdx.x & 31, ty = threadIdx.x >> 5;
#pragma unroll
    for (int i = 0; i < 32; i += 8)
        tile[ty + i][tx] = paw1[(size_t)(k0 + ty + i) * 256 + n0 + tx];
    __syncthreads();
#pragma unroll
    for (int i = 0; i < 32; i += 8) {
        float v = tile[tx][ty + i];
        __nv_bfloat16 hi = __float2bfloat16(v);
        size_t di = (size_t)(n0 + ty + i) * 256 + k0 + tx;
        g_pahi[di] = hi;
        g_palo[di] = __float2bfloat16(v - __bfloat162float(hi));
    }
}

// ---------------- r = relu(edge_attr @ ew1 + eb1) -> fp16 at sorted rows -----
__global__ void r_kernel(const float* __restrict__ ea, const float* __restrict__ ew1,
                         const float* __restrict__ eb1) {
    int e0 = blockIdx.x * 32;
    int j = threadIdx.x;            // 0..127 -> cols 2j, 2j+1
    __shared__ float eas[256];
    __shared__ int spos[32];
    eas[j] = ea[e0 * 8 + j];
    eas[j + 128] = ea[e0 * 8 + 128 + j];
    if (j < 32) spos[j] = g_pos[e0 + j];
    float w0[8], w1[8];
#pragma unroll
    for (int k = 0; k < 8; k++) {
        w0[k] = ew1[k * 256 + 2 * j];
        w1[k] = ew1[k * 256 + 2 * j + 1];
    }
    float b0 = eb1[2 * j], b1 = eb1[2 * j + 1];
    __syncthreads();
    __half2* out = (__half2*)g_R16;
    for (int e = 0; e < 32; e++) {
        float a0 = b0, a1 = b1;
#pragma unroll
        for (int k = 0; k < 8; k++) {
            float v = eas[e * 8 + k];
            a0 += v * w0[k];
            a1 += v * w1[k];
        }
        out[(size_t)spos[e] * 128 + j] =
            __floats2half2_rn(fmaxf(a0, 0.f), fmaxf(a1, 0.f));
    }
}

// ---------------- h = silu([x|c] @ in_w + in_b); also z = h ------------------
__global__ void input_proj(const float* __restrict__ x, const float* __restrict__ c,
                           const int* __restrict__ gid, const int* __restrict__ lid,
                           const float* __restrict__ inw, const float* __restrict__ inb) {
    int n0 = blockIdx.x * 8;
    int j = threadIdx.x;
    __shared__ float xs[8 * 16];
    __shared__ float cs[8];
    if (j < 128) xs[j] = x[n0 * 16 + j];
    if (j < 8) { int n = n0 + j; cs[j] = c[gid[n] * PG + lid[n]]; }
    float w[17];
#pragma unroll
    for (int k = 0; k < 17; k++) w[k] = inw[k * 256 + j];
    float b = inb[j];
    __syncthreads();
    for (int n = 0; n < 8; n++) {
        float acc = b + cs[n] * w[16];
#pragma unroll
        for (int k = 0; k < 16; k++) acc += xs[n * 16 + k] * w[k];
        float v = siluf(acc);
        g_h[(n0 + n) * 256 + j] = v;
        g_z[(n0 + n) * 256 + j] = v;
    }
}

// ---------------- edge GEMM (fp16) + run-length scatter (dst-sorted) --------
__global__ void __launch_bounds__(256, 2) edge_mma(int l) {
    extern __shared__ char sm[];
    uint32_t sbase = smem_u32(sm);
    float* sBias = (float*)(sm + 98304);
    int* sDst = (int*)(sm + 98304 + 512);

    int tid = threadIdx.x, lane = tid & 31, wid = tid >> 5;
    int wm = wid & 3, wn = wid >> 2;
    int col0 = blockIdx.x * 128, row0 = blockIdx.y * 128;

    if (tid < 128) sBias[tid] = g_bl[l * 256 + col0 + tid];
    if (tid >= 128) sDst[tid - 128] = g_dsts[row0 + tid - 128];

    const uint4* Ag = (const uint4*)g_R16 + (size_t)row0 * 32;
    const uint4* Bg = (const uint4*)g_W16 + (size_t)l * 8192 + (size_t)col0 * 32;

    float acc[16][4];
#pragma unroll
    for (int i = 0; i < 16; i++) { acc[i][0] = 0.f; acc[i][1] = 0.f; acc[i][2] = 0.f; acc[i][3] = 0.f; }

    auto issue = [&](int c, int s) {
        uint32_t sa = sbase + s * 32768;
#pragma unroll
        for (int i = 0; i < 4; i++) {
            int elem = tid + 256 * i;
            int r = elem >> 3, u = elem & 7;
            uint32_t o = swz((uint32_t)(r * 128 + u * 16));
            CPA16(sa + o,         Ag + (size_t)r * 32 + c * 8 + u);
            CPA16(sa + 16384 + o, Bg + (size_t)r * 32 + c * 8 + u);
        }
    };

    issue(0, 0); CPC;
    issue(1, 1); CPC;

#pragma unroll
    for (int c = 0; c < 4; c++) {
        int s = (c < 3) ? c : 0;
        if (c < 3) { CPW1; } else { CPW0; }
        __syncthreads();
        uint32_t sa = sbase + s * 32768;
#pragma unroll
        for (int ks = 0; ks < 4; ks++) {
            uint32_t a0[4], a1[4];
            int kb = ks * 32 + ((lane >> 4) << 4);
            LDSM4(a0, sa + swz((uint32_t)((wm * 32 + (lane & 15)) * 128 + kb)));
            LDSM4(a1, sa + swz((uint32_t)((wm * 32 + 16 + (lane & 15)) * 128 + kb)));
#pragma unroll
            for (int np = 0; np < 4; np++) {
                int g = lane >> 3, li = lane & 7;
                int brow = wn * 64 + np * 16 + ((g >> 1) << 3) + li;
                int bkb = ks * 32 + ((g & 1) << 4);
                uint32_t bh[4];
                LDSM4(bh, sa + 16384 + swz((uint32_t)(brow * 128 + bkb)));
#pragma unroll
                for (int t = 0; t < 2; t++) {
                    mma_f16(acc[0 * 8 + np * 2 + t], a0, bh[2 * t], bh[2 * t + 1]);
                    mma_f16(acc[1 * 8 + np * 2 + t], a1, bh[2 * t], bh[2 * t + 1]);
                }
            }
        }
        if (c < 2) { issue(c + 2, c + 2 == 2 ? 2 : 0); CPC; }
    }

    // ---- stage messages in smem ----
    __syncthreads();
    float* msg = (float*)sm;     // [128][MSG_STRIDE] fp32

    int q = lane >> 2;
    int c2 = (lane & 3) * 2;
    int src_[2][2];
#pragma unroll
    for (int mt = 0; mt < 2; mt++)
#pragma unroll
        for (int h = 0; h < 2; h++)
            src_[mt][h] = g_srcs[row0 + wm * 32 + mt * 16 + h * 8 + q];

#pragma unroll
    for (int mt = 0; mt < 2; mt++) {
#pragma unroll
        for (int nt = 0; nt < 8; nt++) {
            float* a = acc[mt * 8 + nt];
            int coln = wn * 64 + nt * 8 + c2;
            int col = col0 + coln;
            float2 bb = *(float2*)(sBias + coln);
#pragma unroll
            for (int h = 0; h < 2; h++) {
                const float2 hv = *(const float2*)(g_h + (size_t)src_[mt][h] * 256 + col);
                float v0 = fmaxf(a[2 * h + 0] + bb.x + hv.x, 0.f);
                float v1 = fmaxf(a[2 * h + 1] + bb.y + hv.y, 0.f);
                int rowloc = wm * 32 + mt * 16 + h * 8 + q;
                *(float2*)(msg + rowloc * MSG_STRIDE + coln) = make_float2(v0, v1);
            }
        }
    }
    __syncthreads();

    // ---- run-length accumulate down sorted-dst rows; one red per run ----
    int cg = tid & 31;
    int seg = tid >> 5;
    int r0g = seg * 16;
    float* zcol = g_z + col0 + cg * 4;
    float4 a4 = *(const float4*)(msg + r0g * MSG_STRIDE + cg * 4);
    int cur = sDst[r0g];
#pragma unroll
    for (int r = 1; r < 16; r++) {
        int d = sDst[r0g + r];
        float4 v = *(const float4*)(msg + (r0g + r) * MSG_STRIDE + cg * 4);
        if (d == cur) {
            a4.x += v.x; a4.y += v.y; a4.z += v.z; a4.w += v.w;
        } else {
            RED4(zcol + (size_t)cur * 256, a4);
            cur = d;
            a4 = v;
        }
    }
    RED4(zcol + (size_t)cur * 256, a4);
}

// ---------------- node0: fp32 z LDG->fp16 convert GEMM (single fp16 term) ----
__global__ void __launch_bounds__(256, 2) node0_mma(int l, const float* __restrict__ cb1) {
    extern __shared__ char sm[];
    uint32_t sbase = smem_u32(sm);
    float* sBias = (float*)(sm + 2 * 16384);

    int tid = threadIdx.x, lane = tid & 31, wid = tid >> 5;
    int wm = wid & 3, wn = wid >> 2;
    int col0 = blockIdx.x * 128, row0 = blockIdx.y * 128;

    if (tid < 128) sBias[tid] = cb1[l * 256 + col0 + tid];

    const float* Az = g_z + (size_t)row0 * 256;
    const uint4* B4 = (const uint4*)(g_cw1_16 + (size_t)l * 65536) + (size_t)col0 * 32;

    float acc[16][4];
#pragma unroll
    for (int i = 0; i < 16; i++) { acc[i][0] = 0.f; acc[i][1] = 0.f; acc[i][2] = 0.f; acc[i][3] = 0.f; }

    float4 pa[2][2];

    auto ldgA = [&](int c) {
#pragma unroll
        for (int i = 0; i < 2; i++) {
            int elem = tid + 256 * i;
            int r = elem >> 2, u = elem & 3;
            const float* src = Az + (size_t)r * 256 + c * 32 + u * 8;
            pa[i][0] = *(const float4*)src;
            pa[i][1] = *(const float4*)(src + 4);
        }
    };
    auto stsA = [&](int s) {
#pragma unroll
        for (int i = 0; i < 2; i++) {
            int elem = tid + 256 * i;
            int r = elem >> 2, u = elem & 3;
            __half2 b0 = __floats2half2_rn(pa[i][0].x, pa[i][0].y);
            __half2 b1 = __floats2half2_rn(pa[i][0].z, pa[i][0].w);
            __half2 b2 = __floats2half2_rn(pa[i][1].x, pa[i][1].y);
            __half2 b3 = __floats2half2_rn(pa[i][1].z, pa[i][1].w);
            uint4 val;
            val.x = *(uint32_t*)&b0; val.y = *(uint32_t*)&b1;
            val.z = *(uint32_t*)&b2; val.w = *(uint32_t*)&b3;
            *(uint4*)(sm + s * 16384 + swz64((uint32_t)(r * 64 + u * 16))) = val;
        }
    };
    auto issueB = [&](int c, int s) {
        uint32_t sa = sbase + s * 16384;
#pragma unroll
        for (int i = 0; i < 2; i++) {
            int elem = tid + 256 * i;
            int r = elem >> 2, u = elem & 3;
            uint32_t o = swz64((uint32_t)(r * 64 + u * 16));
            CPA16(sa + 8192 + o, B4 + (size_t)r * 32 + c * 4 + u);
        }
    };

    ldgA(0);
    issueB(0, 0); CPC;
    issueB(1, 1); CPC;
    stsA(0);
    ldgA(1);
    CPW1;
    __syncthreads();

#pragma unroll 1
    for (int c = 0; c < 8; c++) {
        uint32_t sa = sbase + (c & 1) * 16384;
#pragma unroll
        for (int ks = 0; ks < 2; ks++) {
            uint32_t a0[4], a1[4];
            int kb = ks * 32 + ((lane >> 4) << 4);
            LDSM4(a0, sa + swz64((uint32_t)((wm * 32 + (lane & 15)) * 64 + kb)));
            LDSM4(a1, sa + swz64((uint32_t)((wm * 32 + 16 + (lane & 15)) * 64 + kb)));
#pragma unroll
            for (int np = 0; np < 4; np++) {
                int g = lane >> 3, li = lane & 7;
                int brow = wn * 64 + np * 16 + ((g >> 1) << 3) + li;
                int bkb = ks * 32 + ((g & 1) << 4);
                uint32_t bh[4];
                LDSM4(bh, sa + 8192 + swz64((uint32_t)(brow * 64 + bkb)));
#pragma unroll
                for (int t = 0; t < 2; t++) {
                    mma_f16(acc[0 * 8 + np * 2 + t], a0, bh[2 * t], bh[2 * t + 1]);
                    mma_f16(acc[1 * 8 + np * 2 + t], a1, bh[2 * t], bh[2 * t + 1]);
                }
            }
        }
        if (c < 7) {
            __syncthreads();
            stsA((c + 1) & 1);
            if (c < 6) { ldgA(c + 2); issueB(c + 2, c & 1); CPC; CPW1; }
            else       { CPW0; }
            __syncthreads();
        }
    }

    int q = lane >> 2;
    int c2 = (lane & 3) * 2;
#pragma unroll
    for (int mt = 0; mt < 2; mt++) {
#pragma unroll
        for (int nt = 0; nt < 8; nt++) {
            float* a = acc[mt * 8 + nt];
            int coln = wn * 64 + nt * 8 + c2;
            int col = col0 + coln;
            float2 bb = *(float2*)(sBias + coln);
#pragma unroll
            for (int h = 0; h < 2; h++) {
                int rr = row0 + wm * 32 + mt * 16 + h * 8 + q;
                float v0 = siluf(a[2 * h + 0] + bb.x);
                float v1 = siluf(a[2 * h + 1] + bb.y);
                *(__half2*)(g_t16 + (size_t)rr * 256 + col) = __floats2half2_rn(v0, v1);
            }
        }
    }
}

// ---------------- node1: t16 @ cw2 (fp16 single) -> g_hn (fp32) --------------
__global__ void __launch_bounds__(256, 2) node1_mma(int l, const float* __restrict__ cb2) {
    extern __shared__ char sm[];
    uint32_t sbase = smem_u32(sm);
    float* sBias = (float*)(sm + 98304);

    int tid = threadIdx.x, lane = tid & 31, wid = tid >> 5;
    int wm = wid & 3, wn = wid >> 2;
    int col0 = blockIdx.x * 128, row0 = blockIdx.y * 128;

    if (tid < 128) sBias[tid] = cb2[l * 256 + col0 + tid];

    const uint4* Ag = (const uint4*)g_t16 + (size_t)row0 * 32;
    const uint4* Bg = (const uint4*)(g_cw2_16 + (size_t)l * 65536) + (size_t)col0 * 32;

    float acc[16][4];
#pragma unroll
    for (int i = 0; i < 16; i++) { acc[i][0] = 0.f; acc[i][1] = 0.f; acc[i][2] = 0.f; acc[i][3] = 0.f; }

    auto issue = [&](int c, int s) {
        uint32_t sa = sbase + s * 32768;
#pragma unroll
        for (int i = 0; i < 4; i++) {
            int elem = tid + 256 * i;
            int r = elem >> 3, u = elem & 7;
            uint32_t o = swz((uint32_t)(r * 128 + u * 16));
            CPA16(sa + o,         Ag + (size_t)r * 32 + c * 8 + u);
            CPA16(sa + 16384 + o, Bg + (size_t)r * 32 + c * 8 + u);
        }
    };

    issue(0, 0); CPC;
    issue(1, 1); CPC;

#pragma unroll
    for (int c = 0; c < 4; c++) {
        int s = (c < 3) ? c : 0;
        if (c < 3) { CPW1; } else { CPW0; }
        __syncthreads();
        uint32_t sa = sbase + s * 32768;
#pragma unroll
        for (int ks = 0; ks < 4; ks++) {
            uint32_t a0[4], a1[4];
            int kb = ks * 32 + ((lane >> 4) << 4);
            LDSM4(a0, sa + swz((uint32_t)((wm * 32 + (lane & 15)) * 128 + kb)));
            LDSM4(a1, sa + swz((uint32_t)((wm * 32 + 16 + (lane & 15)) * 128 + kb)));
#pragma unroll
            for (int np = 0; np < 4; np++) {
                int g = lane >> 3, li = lane & 7;
                int brow = wn * 64 + np * 16 + ((g >> 1) << 3) + li;
                int bkb = ks * 32 + ((g & 1) << 4);
                uint32_t bh[4];
                LDSM4(bh, sa + 16384 + swz((uint32_t)(brow * 128 + bkb)));
#pragma unroll
                for (int t = 0; t < 2; t++) {
                    mma_f16(acc[0 * 8 + np * 2 + t], a0, bh[2 * t], bh[2 * t + 1]);
                    mma_f16(acc[1 * 8 + np * 2 + t], a1, bh[2 * t], bh[2 * t + 1]);
                }
            }
        }
        if (c < 2) { issue(c + 2, c + 2 == 2 ? 2 : 0); CPC; }
    }

    int q = lane >> 2;
    int c2 = (lane & 3) * 2;
#pragma unroll
    for (int mt = 0; mt < 2; mt++) {
#pragma unroll
        for (int nt = 0; nt < 8; nt++) {
            float* a = acc[mt * 8 + nt];
            int coln = wn * 64 + nt * 8 + c2;
            int col = col0 + coln;
            float2 bb = *(float2*)(sBias + coln);
#pragma unroll
            for (int h = 0; h < 2; h++) {
                int rr = row0 + wm * 32 + mt * 16 + h * 8 + q;
                if (rr < NN)
                    *(float2*)(g_hn + (size_t)rr * 256 + col) =
                        make_float2(a[2 * h + 0] + bb.x, a[2 * h + 1] + bb.y);
            }
        }
    }
}

// ---------------- scores: zhi @ paw1 (bf16 2-term) -> tanh -> dot paw2 -------
__global__ void __launch_bounds__(256, 2) node_mma2(const float* __restrict__ pab1,
                                                    const float* __restrict__ w2) {
    extern __shared__ char sm[];
    uint32_t sbase = smem_u32(sm);
    float* sBias = (float*)(sm + 98304);
    float* sW2 = (float*)(sm + 98304 + 512);

    int tid = threadIdx.x, lane = tid & 31, wid = tid >> 5;
    int wm = wid & 3, wn = wid >> 2;
    int col0 = blockIdx.x * 128, row0 = blockIdx.y * 128;

    if (tid < 128) { sBias[tid] = pab1[col0 + tid]; sW2[tid] = w2[col0 + tid]; }

    const uint4* A4 = (const uint4*)g_zhi + (size_t)row0 * 32;
    const uint4* Bh4 = (const uint4*)g_pahi + (size_t)col0 * 32;
    const uint4* Bl4 = (const uint4*)g_palo + (size_t)col0 * 32;

    float acc[16][4];
#pragma unroll
    for (int i = 0; i < 16; i++) { acc[i][0] = 0.f; acc[i][1] = 0.f; acc[i][2] = 0.f; acc[i][3] = 0.f; }

    auto issue = [&](int c, int s) {
        uint32_t sa = sbase + s * 49152;
#pragma unroll
        for (int i = 0; i < 4; i++) {
            int elem = tid + 256 * i;
            int r = elem >> 3, u = elem & 7;
            uint32_t o = swz((uint32_t)(r * 128 + u * 16));
            CPA16(sa + o,         A4  + (size_t)r * 32 + c * 8 + u);
            CPA16(sa + 16384 + o, Bh4 + (size_t)r * 32 + c * 8 + u);
            CPA16(sa + 32768 + o, Bl4 + (size_t)r * 32 + c * 8 + u);
        }
    };

    issue(0, 0); CPC;
    issue(1, 1); CPC;

#pragma unroll
    for (int c = 0; c < 4; c++) {
        if (c < 3) { CPW1; } else { CPW0; }
        __syncthreads();
        uint32_t sa = sbase + (c & 1) * 49152;
#pragma unroll
        for (int ks = 0; ks < 4; ks++) {
            uint32_t a0[4], a1[4];
            int kb = ks * 32 + ((lane >> 4) << 4);
            LDSM4(a0, sa + swz((uint32_t)((wm * 32 + (lane & 15)) * 128 + kb)));
            LDSM4(a1, sa + swz((uint32_t)((wm * 32 + 16 + (lane & 15)) * 128 + kb)));
#pragma unroll
            for (int np = 0; np < 4; np++) {
                int g = lane >> 3, li = lane & 7;
                int brow = wn * 64 + np * 16 + ((g >> 1) << 3) + li;
                int bkb = ks * 32 + ((g & 1) << 4);
                uint32_t bh[4], bl[4];
                LDSM4(bh, sa + 16384 + swz((uint32_t)(brow * 128 + bkb)));
                LDSM4(bl, sa + 32768 + swz((uint32_t)(brow * 128 + bkb)));
#pragma unroll
                for (int t = 0; t < 2; t++) {
                    mma_bf16(acc[0 * 8 + np * 2 + t], a0, bh[2 * t], bh[2 * t + 1]);
                    mma_bf16(acc[0 * 8 + np * 2 + t], a0, bl[2 * t], bl[2 * t + 1]);
                    mma_bf16(acc[1 * 8 + np * 2 + t], a1, bh[2 * t], bh[2 * t + 1]);
                    mma_bf16(acc[1 * 8 + np * 2 + t], a1, bl[2 * t], bl[2 * t + 1]);
                }
            }
        }
        if (c < 2) { __syncthreads(); issue(c + 2, c & 1); CPC; }
    }

    int q = lane >> 2;
    int c2 = (lane & 3) * 2;
#pragma unroll
    for (int mt = 0; mt < 2; mt++) {
#pragma unroll
        for (int h = 0; h < 2; h++) {
            int rr = row0 + wm * 32 + mt * 16 + h * 8 + q;
            float part = 0.f;
#pragma unroll
            for (int nt = 0; nt < 8; nt++) {
                float* a = acc[mt * 8 + nt];
                int coln = wn * 64 + nt * 8 + c2;
                part += tanhf(a[2 * h + 0] + sBias[coln])     * sW2[coln];
                part += tanhf(a[2 * h + 1] + sBias[coln + 1]) * sW2[coln + 1];
            }
            part += __shfl_xor_sync(~0u, part, 1);
            part += __shfl_xor_sync(~0u, part, 2);
            if ((lane & 3) == 0 && rr < NN) atomicAdd(&g_scores[rr], part);
        }
    }
}

// ---------------- LayerNorm + residual silu update; z = h_next; bf16 h -------
__global__ void ln_update(int l, const float* __restrict__ lng, const float* __restrict__ lnb) {
    int warp = threadIdx.x >> 5, lane = threadIdx.x & 31;
    int n = blockIdx.x * 8 + warp;
    const float* g = lng + l * 256;
    const float* b = lnb + l * 256;
    const float* row = g_hn + (size_t)n * 256;
    float v[8];
    float s = 0.f, ss = 0.f;
#pragma unroll
    for (int t = 0; t < 8; t++) {
        v[t] = row[lane + 32 * t];
        s += v[t]; ss += v[t] * v[t];
    }
#pragma unroll
    for (int o = 16; o > 0; o >>= 1) {
        s += __shfl_xor_sync(~0u, s, o);
        ss += __shfl_xor_sync(~0u, ss, o);
    }
    float m = s * (1.f / 256.f);
    float var = ss * (1.f / 256.f) - m * m;
    float r = rsqrtf(var + 1e-5f);
    float* hrow = g_h + (size_t)n * 256;
    float* zrow = g_z + (size_t)n * 256;
#pragma unroll
    for (int t = 0; t < 8; t++) {
        int cidx = lane + 32 * t;
        float u = (v[t] - m) * r * g[cidx] + b[cidx];
        float nh = hrow[cidx] + siluf(u);
        hrow[cidx] = nh;
        zrow[cidx] = nh;
        if (l == LL - 1) g_zhi[(size_t)n * 256 + cidx] = __float2bfloat16(nh);
    }
}

// ---------------- global softmax stats --------------------------------------
__global__ void softmax_stats() {
    __shared__ float red[1024];
    int t = threadIdx.x;
    float m = -1e30f;
    for (int i = t; i < NN; i += 1024) m = fmaxf(m, g_scores[i]);
    red[t] = m;
    __syncthreads();
    for (int o = 512; o > 0; o >>= 1) {
        if (t < o) red[t] = fmaxf(red[t], red[t + o]);
        __syncthreads();
    }
    float gmax = red[0];
    __syncthreads();
    float s = 0.f;
    for (int i = t; i < NN; i += 1024) s += expf(g_scores[i] - gmax);
    red[t] = s;
    __syncthreads();
    for (int o = 512; o > 0; o >>= 1) {
        if (t < o) red[t] += red[t + o];
        __syncthreads();
    }
    if (t == 0) { g_stats[0] = gmax; g_stats[1] = red[0]; }
}

// ---------------- per-graph renormalized attention --------------------------
__global__ void seg_attn() {
    int g = blockIdx.x, t = threadIdx.x;
    float gmax = g_stats[0], Z = g_stats[1];
    int base = g * PG;
    float s = 0.f;
    for (int i = t; i < PG; i += 256) s += expf(g_scores[base + i] - gmax);
    __shared__ float red[256];
    red[t] = s;
    __syncthreads();
    for (int o = 128; o > 0; o >>= 1) {
        if (t < o) red[t] += red[t + o];
        __syncthreads();
    }
    float denom = red[0] / Z + 1e-8f;
    float scale = 1.f / (Z * denom);
    for (int i = t; i < PG; i += 256) g_attn[base + i] = expf(g_scores[base + i] - gmax) * scale;
    g_pooled[g * 256 + t] = 0.f;
}

// ---------------- weighted pooling ------------------------------------------
__global__ void pool_kernel() {
    int g = blockIdx.x, chunk = blockIdx.y, j = threadIdx.x;
    int base = g * PG + chunk * 50;
    float acc = 0.f;
    for (int i = 0; i < 50; i++)
        acc += g_h[(size_t)(base + i) * 256 + j] * g_attn[base + i];
    atomicAdd(&g_pooled[g * 256 + j], acc);
}

// ---------------- head -------------------------------------------------------
__global__ void head_kernel(const float* __restrict__ hw1, const float* __restrict__ hb1,
                            const float* __restrict__ hw2, const float* __restrict__ hb2,
                            float* __restrict__ out) {
    int g = blockIdx.x, j = threadIdx.x;
    __shared__ float ps[256];
    __shared__ float red[256];
    ps[j] = g_pooled[g * 256 + j];
    __syncthreads();
    float acc = hb1[j];
#pragma unroll 8
    for (int k = 0; k < 256; k++) acc += ps[k] * hw1[k * 256 + j];
    red[j] = siluf(acc) * hw2[j];
    __syncthreads();
    for (int o = 128; o > 0; o >>= 1) {
        if (j < o) red[j] += red[j + o];
        __syncthreads();
    }
    if (j == 0) out[g] = red[0] + hb2[0];
}

// ---------------- launch -----------------------------------------------------
extern "C" void kernel_launch(void* const* d_in, const int* in_sizes, int n_in,
                              void* d_out, int out_size) {
    const float* x    = (const float*)d_in[0];
    const float* ea   = (const float*)d_in[1];
    const float* c    = (const float*)d_in[2];
    const int*   eidx = (const int*)  d_in[3];
    const int*   gid  = (const int*)  d_in[4];
    const int*   lid  = (const int*)  d_in[5];
    const float* ew1  = (const float*)d_in[6];
    const float* eb1  = (const float*)d_in[7];
    const float* ew2  = (const float*)d_in[8];
    const float* eb2  = (const float*)d_in[9];
    const float* inw  = (const float*)d_in[10];
    const float* inb  = (const float*)d_in[11];
    const float* lin_w = (const float*)d_in[12];
    const float* lin_b = (const float*)d_in[13];
    const float* cw1  = (const float*)d_in[14];
    const float* cb1  = (const float*)d_in[15];
    const float* cw2  = (const float*)d_in[16];
    const float* cb2  = (const float*)d_in[17];
    const float* lng  = (const float*)d_in[18];
    const float* lnb  = (const float*)d_in[19];
    const float* paw1 = (const float*)d_in[20];
    const float* pab1 = (const float*)d_in[21];
    const float* paw2 = (const float*)d_in[22];
    const float* pab2 = (const float*)d_in[23];
    const float* hw1  = (const float*)d_in[24];
    const float* hb1  = (const float*)d_in[25];
    const float* hw2  = (const float*)d_in[26];
    const float* hb2  = (const float*)d_in[27];
    float* out = (float*)d_out;

    static int attr_done = 0;
    static cudaStream_t s1 = 0;
    static cudaEvent_t evF = 0, evJ = 0;
    if (!attr_done) {
        cudaFuncSetAttribute((const void*)edge_mma,
                             cudaFuncAttributeMaxDynamicSharedMemorySize, PIPE_SMEM);
        cudaFuncSetAttribute((const void*)node0_mma,
                             cudaFuncAttributeMaxDynamicSharedMemorySize, NODE0_SMEM);
        cudaFuncSetAttribute((const void*)node1_mma,
                             cudaFuncAttributeMaxDynamicSharedMemorySize, PIPE_SMEM);
        cudaFuncSetAttribute((const void*)node_mma2,
                             cudaFuncAttributeMaxDynamicSharedMemorySize, PIPE_SMEM);
        cudaStreamCreateWithFlags(&s1, cudaStreamNonBlocking);
        cudaEventCreateWithFlags(&evF, cudaEventDisableTiming);
        cudaEventCreateWithFlags(&evJ, cudaEventDisableTiming);
        attr_done = 1;
    }

    // fork: prep chain (independent of edge sort) runs on s1
    cudaEventRecord(evF, 0);
    cudaStreamWaitEvent(s1, evF, 0);
    prep_W<<<LL * 256, 256, 0, s1>>>(ew2, lin_w);
    prep_bl<<<LL, 256, 0, s1>>>(eb2, lin_w, lin_b);
    prep_nw<<<dim3(8, 8, LL * 2), 256, 0, s1>>>(cw1, cw2);
    prep_pw<<<dim3(8, 8), 256, 0, s1>>>(paw1);
    input_proj<<<NN / 8, 256, 0, s1>>>(x, c, gid, lid, inw, inb);
    cudaEventRecord(evJ, s1);

    // default stream: dst counting sort + R generation
    zero_init<<<(NN + 255) / 256, 256>>>(pab2);
    hist_kernel<<<EE / 256, 256>>>(eidx);
    scan_kernel<<<1, 1024>>>();
    scatter_kernel<<<EE / 256, 256>>>(eidx);
    r_kernel<<<EE / 32, 128>>>(ea, ew1, eb1);

    // join: layer loop needs both chains
    cudaStreamWaitEvent(0, evJ, 0);

    for (int l = 0; l < LL; l++) {
        edge_mma<<<dim3(2, EE / 128), 256, PIPE_SMEM>>>(l);
        node0_mma<<<dim3(2, NPAD / 128), 256, NODE0_SMEM>>>(l, cb1);
        node1_mma<<<dim3(2, NPAD / 128), 256, PIPE_SMEM>>>(l, cb2);
        ln_update<<<NN / 8, 256>>>(l, lng, lnb);
    }

    node_mma2<<<dim3(2, NPAD / 128), 256, PIPE_SMEM>>>(pab1, paw2);
    softmax_stats<<<1, 1024>>>();
    seg_attn<<<GB, 256>>>();
    pool_kernel<<<dim3(GB, PG / 50), 256>>>();
    head_kernel<<<GB, 256>>>(hw1, hb1, hw2, hb2, out);
    (void)in_sizes; (void)n_in; (void)out_size;
}

// round 16
// speedup vs baseline: 1.0286x; 1.0058x over previous
#include <cuda_runtime.h>
#include <cuda_bf16.h>
#include <cuda_fp16.h>
#include <math.h>
#include <stdint.h>

#define NN 20000
#define EE 320000
#define HH 256
#define LL 6
#define GB 20
#define PG 1000
#define NPAD 20096   // 157*128

// ---------------- scratch ----------------------------------------------------
__device__ __half g_R16[(size_t)EE * HH];        // fp16 edge features (dst-sorted rows)
__device__ __half g_W16[LL * HH * HH];           // fp16 folded edge weights [l][n][k]
__device__ float g_bl[LL * HH];
__device__ float g_h[NN * HH];
__device__ float g_z[NPAD * HH];                 // fp32 accumulation target (pad rows stay 0)
__device__ float g_hn[NN * HH];
__device__ __nv_bfloat16 g_zhi[NPAD * HH];       // bf16 of final h (for scores)
__device__ __half g_t16[NPAD * HH];              // fp16 intermediate t
__device__ __half g_cw1_16[LL * HH * HH];        // fp16 node weights [l][n][k]
__device__ __half g_cw2_16[LL * HH * HH];
__device__ __nv_bfloat16 g_pahi[HH * HH], g_palo[HH * HH];  // paw1^T split (scores)
__device__ float g_scores[NN];
__device__ float g_attn[NN];
__device__ float g_pooled[GB * HH];
// dst-sort structures (rebuilt every launch)
__device__ int g_cnt[NN];
__device__ int g_pos[EE];
__device__ int g_srcs[EE];
__device__ int g_dsts[EE];

__device__ __forceinline__ float siluf(float x) { return x / (1.f + expf(-x)); }

__device__ __forceinline__ uint32_t smem_u32(const void* p) {
    uint32_t a;
    asm("{ .reg .u64 t; cvta.to.shared.u64 t, %1; cvt.u32.u64 %0, t; }" : "=r"(a) : "l"(p));
    return a;
}
__device__ __forceinline__ uint32_t swz(uint32_t o)   { return o ^ ((o >> 3) & 0x70); }
__device__ __forceinline__ uint32_t swz64(uint32_t o) { return o ^ ((o >> 3) & 0x30); }

#define LDSM4(r, addr) \
    asm volatile("ldmatrix.sync.aligned.m8n8.x4.shared.b16 {%0,%1,%2,%3}, [%4];" \
        : "=r"((r)[0]), "=r"((r)[1]), "=r"((r)[2]), "=r"((r)[3]) : "r"(addr))

__device__ __forceinline__ void mma_bf16(float* d, const uint32_t* a, uint32_t b0, uint32_t b1) {
    asm volatile("mma.sync.aligned.m16n8k16.row.col.f32.bf16.bf16.f32 "
        "{%0,%1,%2,%3}, {%4,%5,%6,%7}, {%8,%9}, {%0,%1,%2,%3};"
        : "+f"(d[0]), "+f"(d[1]), "+f"(d[2]), "+f"(d[3])
        : "r"(a[0]), "r"(a[1]), "r"(a[2]), "r"(a[3]), "r"(b0), "r"(b1));
}
__device__ __forceinline__ void mma_f16(float* d, const uint32_t* a, uint32_t b0, uint32_t b1) {
    asm volatile("mma.sync.aligned.m16n8k16.row.col.f32.f16.f16.f32 "
        "{%0,%1,%2,%3}, {%4,%5,%6,%7}, {%8,%9}, {%0,%1,%2,%3};"
        : "+f"(d[0]), "+f"(d[1]), "+f"(d[2]), "+f"(d[3])
        : "r"(a[0]), "r"(a[1]), "r"(a[2]), "r"(a[3]), "r"(b0), "r"(b1));
}

#define CPA16(d, s) asm volatile("cp.async.cg.shared.global [%0], [%1], 16;" :: "r"(d), "l"(s) : "memory")
#define CPC        asm volatile("cp.async.commit_group;" ::: "memory")
#define CPW1       asm volatile("cp.async.wait_group 1;" ::: "memory")
#define CPW0       asm volatile("cp.async.wait_group 0;" ::: "memory")

#define RED4(p, v) asm volatile("red.global.add.v4.f32 [%0], {%1,%2,%3,%4};" \
    :: "l"(p), "f"((v).x), "f"((v).y), "f"((v).z), "f"((v).w) : "memory")

#define PIPE_SMEM (98304 + 1024)
#define NODE0_SMEM (2 * 16384 + 512)
#define MSG_STRIDE 136   // floats per msg row: 128 + 8 pad

// ---------------- dst counting sort (edge_index constant across layers) ------
__global__ void zero_init(const float* __restrict__ pab2) {
    int i = blockIdx.x * 256 + threadIdx.x;
    if (i < NN) { g_cnt[i] = 0; g_scores[i] = pab2[0]; }
}
__global__ void hist_kernel(const int* __restrict__ eidx) {
    int i = blockIdx.x * 256 + threadIdx.x;
    atomicAdd(&g_cnt[eidx[EE + i]], 1);
}
__global__ void scan_kernel() {
    __shared__ int sums[1024];
    int t = threadIdx.x;
    int base = t * 20;
    int local[20];
    int s = 0;
#pragma unroll
    for (int i = 0; i < 20; i++) {
        int b = base + i;
        int v = (b < NN) ? g_cnt[b] : 0;
        local[i] = s;
        s += v;
    }
    sums[t] = s;
    __syncthreads();
    for (int o = 1; o < 1024; o <<= 1) {
        int v = (t >= o) ? sums[t - o] : 0;
        __syncthreads();
        sums[t] += v;
        __syncthreads();
    }
    int excl = (t == 0) ? 0 : sums[t - 1];
#pragma unroll
    for (int i = 0; i < 20; i++) {
        int b = base + i;
        if (b < NN) g_cnt[b] = excl + local[i];
    }
}
__global__ void scatter_kernel(const int* __restrict__ eidx) {
    int i = blockIdx.x * 256 + threadIdx.x;
    int d = eidx[EE + i];
    int p = atomicAdd(&g_cnt[d], 1);
    g_pos[i] = p;
    g_srcs[p] = eidx[i];
    g_dsts[p] = d;
}

// ---------------- weight folding: W16_l = (ew2 @ lin_w[l])^T fp16 -----------
__global__ void prep_W(const float* __restrict__ ew2, const float* __restrict__ lin_w) {
    int l = blockIdx.x >> 8;
    int i = blockIdx.x & 255;   // K index
    int j = threadIdx.x;        // N index
    __shared__ float er[256];
    er[j] = ew2[i * 256 + j];
    __syncthreads();
    const float* lw = lin_w + l * 65536;
    float acc = 0.f;
#pragma unroll 8
    for (int m = 0; m < 256; m++) acc += er[m] * lw[m * 256 + j];
    g_W16[l * 65536 + j * 256 + i] = __float2half(acc);
}

__global__ void prep_bl(const float* __restrict__ eb2, const float* __restrict__ lin_w,
                        const float* __restrict__ lin_b) {
    int l = blockIdx.x;
    int j = threadIdx.x;
    const float* lw = lin_w + l * 65536;
    float acc = lin_b[l * 256 + j];
#pragma unroll 8
    for (int m = 0; m < 256; m++) acc += eb2[m] * lw[m * 256 + j];
    g_bl[l * 256 + j] = acc;
}

// ---------------- node weight transpose -> fp16 (tiled, coalesced) ----------
__global__ void prep_nw(const float* __restrict__ cw1, const float* __restrict__ cw2) {
    __shared__ float tile[32][33];
    int l = blockIdx.z >> 1, m = blockIdx.z & 1;
    const float* src = (m ? cw2 : cw1) + (size_t)l * 65536;
    __half* dst = (m ? g_cw2_16 : g_cw1_16) + (size_t)l * 65536;
    int n0 = blockIdx.x * 32, k0 = blockIdx.y * 32;
    int tx = threadIdx.x & 31, ty = threadIdx.x >> 5;   // 256 threads = 32x8
#pragma unroll
    for (int i = 0; i < 32; i += 8)
        tile[ty + i][tx] = src[(size_t)(k0 + ty + i) * 256 + n0 + tx];
    __syncthreads();
#pragma unroll
    for (int i = 0; i < 32; i += 8)
        dst[(size_t)(n0 + ty + i) * 256 + k0 + tx] = __float2half(tile[tx][ty + i]);
}

// ---------------- pool-attn weight transpose + bf16 split (tiled) -----------
__global__ void prep_pw(const float* __restrict__ paw1) {
    __shared__ float tile[32][33];
    int n0 = blockIdx.x * 32, k0 = blockIdx.y * 32;
    int tx = threadIdx.x & 31, ty = threadIdx.x >> 5;
#pragma unroll
    for (int i = 0; i < 32; i += 8)
        tile[ty + i][tx] = paw1[(size_t)(k0 + ty + i) * 256 + n0 + tx];
    __syncthreads();
#pragma unroll
    for (int i = 0; i < 32; i += 8) {
        float v = tile[tx][ty + i];
        __nv_bfloat16 hi = __float2bfloat16(v);
        size_t di = (size_t)(n0 + ty + i) * 256 + k0 + tx;
        g_pahi[di] = hi;
        g_palo[di] = __float2bfloat16(v - __bfloat162float(hi));
    }
}

// ---------------- r = relu(edge_attr @ ew1 + eb1) -> fp16 at sorted rows -----
__global__ void r_kernel(const float* __restrict__ ea, const float* __restrict__ ew1,
                         const float* __restrict__ eb1) {
    int e0 = blockIdx.x * 32;
    int j = threadIdx.x;            // 0..127 -> cols 2j, 2j+1
    __shared__ float eas[256];
    __shared__ int spos[32];
    eas[j] = ea[e0 * 8 + j];
    eas[j + 128] = ea[e0 * 8 + 128 + j];
    if (j < 32) spos[j] = g_pos[e0 + j];
    float w0[8], w1[8];
#pragma unroll
    for (int k = 0; k < 8; k++) {
        w0[k] = ew1[k * 256 + 2 * j];
        w1[k] = ew1[k * 256 + 2 * j + 1];
    }
    float b0 = eb1[2 * j], b1 = eb1[2 * j + 1];
    __syncthreads();
    __half2* out = (__half2*)g_R16;
    for (int e = 0; e < 32; e++) {
        float a0 = b0, a1 = b1;
#pragma unroll
        for (int k = 0; k < 8; k++) {
            float v = eas[e * 8 + k];
            a0 += v * w0[k];
            a1 += v * w1[k];
        }
        out[(size_t)spos[e] * 128 + j] =
            __floats2half2_rn(fmaxf(a0, 0.f), fmaxf(a1, 0.f));
    }
}

// ---------------- h = silu([x|c] @ in_w + in_b); also z = h ------------------
__global__ void input_proj(const float* __restrict__ x, const float* __restrict__ c,
                           const int* __restrict__ gid, const int* __restrict__ lid,
                           const float* __restrict__ inw, const float* __restrict__ inb) {
    int n0 = blockIdx.x * 8;
    int j = threadIdx.x;
    __shared__ float xs[8 * 16];
    __shared__ float cs[8];
    if (j < 128) xs[j] = x[n0 * 16 + j];
    if (j < 8) { int n = n0 + j; cs[j] = c[gid[n] * PG + lid[n]]; }
    float w[17];
#pragma unroll
    for (int k = 0; k < 17; k++) w[k] = inw[k * 256 + j];
    float b = inb[j];
    __syncthreads();
    for (int n = 0; n < 8; n++) {
        float acc = b + cs[n] * w[16];
#pragma unroll
        for (int k = 0; k < 16; k++) acc += xs[n * 16 + k] * w[k];
        float v = siluf(acc);
        g_h[(n0 + n) * 256 + j] = v;
        g_z[(n0 + n) * 256 + j] = v;
    }
}

// ---------------- edge GEMM (fp16) + run-length scatter (dst-sorted) --------
__global__ void __launch_bounds__(256, 2) edge_mma(int l) {
    extern __shared__ char sm[];
    uint32_t sbase = smem_u32(sm);
    float* sBias = (float*)(sm + 98304);
    int* sDst = (int*)(sm + 98304 + 512);

    int tid = threadIdx.x, lane = tid & 31, wid = tid >> 5;
    int wm = wid & 3, wn = wid >> 2;
    int col0 = blockIdx.x * 128, row0 = blockIdx.y * 128;

    if (tid < 128) sBias[tid] = g_bl[l * 256 + col0 + tid];
    if (tid >= 128) sDst[tid - 128] = g_dsts[row0 + tid - 128];

    const uint4* Ag = (const uint4*)g_R16 + (size_t)row0 * 32;
    const uint4* Bg = (const uint4*)g_W16 + (size_t)l * 8192 + (size_t)col0 * 32;

    float acc[16][4];
#pragma unroll
    for (int i = 0; i < 16; i++) { acc[i][0] = 0.f; acc[i][1] = 0.f; acc[i][2] = 0.f; acc[i][3] = 0.f; }

    auto issue = [&](int c, int s) {
        uint32_t sa = sbase + s * 32768;
#pragma unroll
        for (int i = 0; i < 4; i++) {
            int elem = tid + 256 * i;
            int r = elem >> 3, u = elem & 7;
            uint32_t o = swz((uint32_t)(r * 128 + u * 16));
            CPA16(sa + o,         Ag + (size_t)r * 32 + c * 8 + u);
            CPA16(sa + 16384 + o, Bg + (size_t)r * 32 + c * 8 + u);
        }
    };

    issue(0, 0); CPC;
    issue(1, 1); CPC;

#pragma unroll
    for (int c = 0; c < 4; c++) {
        int s = (c < 3) ? c : 0;
        if (c < 3) { CPW1; } else { CPW0; }
        __syncthreads();
        uint32_t sa = sbase + s * 32768;
#pragma unroll
        for (int ks = 0; ks < 4; ks++) {
            uint32_t a0[4], a1[4];
            int kb = ks * 32 + ((lane >> 4) << 4);
            LDSM4(a0, sa + swz((uint32_t)((wm * 32 + (lane & 15)) * 128 + kb)));
            LDSM4(a1, sa + swz((uint32_t)((wm * 32 + 16 + (lane & 15)) * 128 + kb)));
#pragma unroll
            for (int np = 0; np < 4; np++) {
                int g = lane >> 3, li = lane & 7;
                int brow = wn * 64 + np * 16 + ((g >> 1) << 3) + li;
                int bkb = ks * 32 + ((g & 1) << 4);
                uint32_t bh[4];
                LDSM4(bh, sa + 16384 + swz((uint32_t)(brow * 128 + bkb)));
#pragma unroll
                for (int t = 0; t < 2; t++) {
                    mma_f16(acc[0 * 8 + np * 2 + t], a0, bh[2 * t], bh[2 * t + 1]);
                    mma_f16(acc[1 * 8 + np * 2 + t], a1, bh[2 * t], bh[2 * t + 1]);
                }
            }
        }
        if (c < 2) { issue(c + 2, c + 2 == 2 ? 2 : 0); CPC; }
    }

    // ---- stage messages in smem ----
    __syncthreads();
    float* msg = (float*)sm;     // [128][MSG_STRIDE] fp32

    int q = lane >> 2;
    int c2 = (lane & 3) * 2;
    int src_[2][2];
#pragma unroll
    for (int mt = 0; mt < 2; mt++)
#pragma unroll
        for (int h = 0; h < 2; h++)
            src_[mt][h] = g_srcs[row0 + wm * 32 + mt * 16 + h * 8 + q];

#pragma unroll
    for (int mt = 0; mt < 2; mt++) {
#pragma unroll
        for (int nt = 0; nt < 8; nt++) {
            float* a = acc[mt * 8 + nt];
            int coln = wn * 64 + nt * 8 + c2;
            int col = col0 + coln;
            float2 bb = *(float2*)(sBias + coln);
#pragma unroll
            for (int h = 0; h < 2; h++) {
                const float2 hv = *(const float2*)(g_h + (size_t)src_[mt][h] * 256 + col);
                float v0 = fmaxf(a[2 * h + 0] + bb.x + hv.x, 0.f);
                float v1 = fmaxf(a[2 * h + 1] + bb.y + hv.y, 0.f);
                int rowloc = wm * 32 + mt * 16 + h * 8 + q;
                *(float2*)(msg + rowloc * MSG_STRIDE + coln) = make_float2(v0, v1);
            }
        }
    }
    __syncthreads();

    // ---- run-length accumulate down sorted-dst rows; one red per run ----
    int cg = tid & 31;
    int seg = tid >> 5;
    int r0g = seg * 16;
    float* zcol = g_z + col0 + cg * 4;
    float4 a4 = *(const float4*)(msg + r0g * MSG_STRIDE + cg * 4);
    int cur = sDst[r0g];
#pragma unroll
    for (int r = 1; r < 16; r++) {
        int d = sDst[r0g + r];
        float4 v = *(const float4*)(msg + (r0g + r) * MSG_STRIDE + cg * 4);
        if (d == cur) {
            a4.x += v.x; a4.y += v.y; a4.z += v.z; a4.w += v.w;
        } else {
            RED4(zcol + (size_t)cur * 256, a4);
            cur = d;
            a4 = v;
        }
    }
    RED4(zcol + (size_t)cur * 256, a4);
}

// ---------------- node0: fp32 z LDG->fp16 convert GEMM (single fp16 term) ----
__global__ void __launch_bounds__(256, 2) node0_mma(int l, const float* __restrict__ cb1) {
    extern __shared__ char sm[];
    uint32_t sbase = smem_u32(sm);
    float* sBias = (float*)(sm + 2 * 16384);

    int tid = threadIdx.x, lane = tid & 31, wid = tid >> 5;
    int wm = wid & 3, wn = wid >> 2;
    int col0 = blockIdx.x * 128, row0 = blockIdx.y * 128;

    if (tid < 128) sBias[tid] = cb1[l * 256 + col0 + tid];

    const float* Az = g_z + (size_t)row0 * 256;
    const uint4* B4 = (const uint4*)(g_cw1_16 + (size_t)l * 65536) + (size_t)col0 * 32;

    float acc[16][4];
#pragma unroll
    for (int i = 0; i < 16; i++) { acc[i][0] = 0.f; acc[i][1] = 0.f; acc[i][2] = 0.f; acc[i][3] = 0.f; }

    float4 pa[2][2];

    auto ldgA = [&](int c) {
#pragma unroll
        for (int i = 0; i < 2; i++) {
            int elem = tid + 256 * i;
            int r = elem >> 2, u = elem & 3;
            const float* src = Az + (size_t)r * 256 + c * 32 + u * 8;
            pa[i][0] = *(const float4*)src;
            pa[i][1] = *(const float4*)(src + 4);
        }
    };
    auto stsA = [&](int s) {
#pragma unroll
        for (int i = 0; i < 2; i++) {
            int elem = tid + 256 * i;
            int r = elem >> 2, u = elem & 3;
            __half2 b0 = __floats2half2_rn(pa[i][0].x, pa[i][0].y);
            __half2 b1 = __floats2half2_rn(pa[i][0].z, pa[i][0].w);
            __half2 b2 = __floats2half2_rn(pa[i][1].x, pa[i][1].y);
            __half2 b3 = __floats2half2_rn(pa[i][1].z, pa[i][1].w);
            uint4 val;
            val.x = *(uint32_t*)&b0; val.y = *(uint32_t*)&b1;
            val.z = *(uint32_t*)&b2; val.w = *(uint32_t*)&b3;
            *(uint4*)(sm + s * 16384 + swz64((uint32_t)(r * 64 + u * 16))) = val;
        }
    };
    auto issueB = [&](int c, int s) {
        uint32_t sa = sbase + s * 16384;
#pragma unroll
        for (int i = 0; i < 2; i++) {
            int elem = tid + 256 * i;
            int r = elem >> 2, u = elem & 3;
            uint32_t o = swz64((uint32_t)(r * 64 + u * 16));
            CPA16(sa + 8192 + o, B4 + (size_t)r * 32 + c * 4 + u);
        }
    };

    ldgA(0);
    issueB(0, 0); CPC;
    issueB(1, 1); CPC;
    stsA(0);
    ldgA(1);
    CPW1;
    __syncthreads();

#pragma unroll 1
    for (int c = 0; c < 8; c++) {
        uint32_t sa = sbase + (c & 1) * 16384;
#pragma unroll
        for (int ks = 0; ks < 2; ks++) {
            uint32_t a0[4], a1[4];
            int kb = ks * 32 + ((lane >> 4) << 4);
            LDSM4(a0, sa + swz64((uint32_t)((wm * 32 + (lane & 15)) * 64 + kb)));
            LDSM4(a1, sa + swz64((uint32_t)((wm * 32 + 16 + (lane & 15)) * 64 + kb)));
#pragma unroll
            for (int np = 0; np < 4; np++) {
                int g = lane >> 3, li = lane & 7;
                int brow = wn * 64 + np * 16 + ((g >> 1) << 3) + li;
                int bkb = ks * 32 + ((g & 1) << 4);
                uint32_t bh[4];
                LDSM4(bh, sa + 8192 + swz64((uint32_t)(brow * 64 + bkb)));
#pragma unroll
                for (int t = 0; t < 2; t++) {
                    mma_f16(acc[0 * 8 + np * 2 + t], a0, bh[2 * t], bh[2 * t + 1]);
                    mma_f16(acc[1 * 8 + np * 2 + t], a1, bh[2 * t], bh[2 * t + 1]);
                }
            }
        }
        if (c < 7) {
            __syncthreads();
            stsA((c + 1) & 1);
            if (c < 6) { ldgA(c + 2); issueB(c + 2, c & 1); CPC; CPW1; }
            else       { CPW0; }
            __syncthreads();
        }
    }

    int q = lane >> 2;
    int c2 = (lane & 3) * 2;
#pragma unroll
    for (int mt = 0; mt < 2; mt++) {
#pragma unroll
        for (int nt = 0; nt < 8; nt++) {
            float* a = acc[mt * 8 + nt];
            int coln = wn * 64 + nt * 8 + c2;
            int col = col0 + coln;
            float2 bb = *(float2*)(sBias + coln);
#pragma unroll
            for (int h = 0; h < 2; h++) {
                int rr = row0 + wm * 32 + mt * 16 + h * 8 + q;
                float v0 = siluf(a[2 * h + 0] + bb.x);
                float v1 = siluf(a[2 * h + 1] + bb.y);
                *(__half2*)(g_t16 + (size_t)rr * 256 + col) = __floats2half2_rn(v0, v1);
            }
        }
    }
}

// ---------------- node1: t16 @ cw2 (fp16 single) -> g_hn (fp32) --------------
__global__ void __launch_bounds__(256, 2) node1_mma(int l, const float* __restrict__ cb2) {
    extern __shared__ char sm[];
    uint32_t sbase = smem_u32(sm);
    float* sBias = (float*)(sm + 98304);

    int tid = threadIdx.x, lane = tid & 31, wid = tid >> 5;
    int wm = wid & 3, wn = wid >> 2;
    int col0 = blockIdx.x * 128, row0 = blockIdx.y * 128;

    if (tid < 128) sBias[tid] = cb2[l * 256 + col0 + tid];

    const uint4* Ag = (const uint4*)g_t16 + (size_t)row0 * 32;
    const uint4* Bg = (const uint4*)(g_cw2_16 + (size_t)l * 65536) + (size_t)col0 * 32;

    float acc[16][4];
#pragma unroll
    for (int i = 0; i < 16; i++) { acc[i][0] = 0.f; acc[i][1] = 0.f; acc[i][2] = 0.f; acc[i][3] = 0.f; }

    auto issue = [&](int c, int s) {
        uint32_t sa = sbase + s * 32768;
#pragma unroll
        for (int i = 0; i < 4; i++) {
            int elem = tid + 256 * i;
            int r = elem >> 3, u = elem & 7;
            uint32_t o = swz((uint32_t)(r * 128 + u * 16));
            CPA16(sa + o,         Ag + (size_t)r * 32 + c * 8 + u);
            CPA16(sa + 16384 + o, Bg + (size_t)r * 32 + c * 8 + u);
        }
    };

    issue(0, 0); CPC;
    issue(1, 1); CPC;

#pragma unroll
    for (int c = 0; c < 4; c++) {
        int s = (c < 3) ? c : 0;
        if (c < 3) { CPW1; } else { CPW0; }
        __syncthreads();
        uint32_t sa = sbase + s * 32768;
#pragma unroll
        for (int ks = 0; ks < 4; ks++) {
            uint32_t a0[4], a1[4];
            int kb = ks * 32 + ((lane >> 4) << 4);
            LDSM4(a0, sa + swz((uint32_t)((wm * 32 + (lane & 15)) * 128 + kb)));
            LDSM4(a1, sa + swz((uint32_t)((wm * 32 + 16 + (lane & 15)) * 128 + kb)));
#pragma unroll
            for (int np = 0; np < 4; np++) {
                int g = lane >> 3, li = lane & 7;
                int brow = wn * 64 + np * 16 + ((g >> 1) << 3) + li;
                int bkb = ks * 32 + ((g & 1) << 4);
                uint32_t bh[4];
                LDSM4(bh, sa + 16384 + swz((uint32_t)(brow * 128 + bkb)));
#pragma unroll
                for (int t = 0; t < 2; t++) {
                    mma_f16(acc[0 * 8 + np * 2 + t], a0, bh[2 * t], bh[2 * t + 1]);
                    mma_f16(acc[1 * 8 + np * 2 + t], a1, bh[2 * t], bh[2 * t + 1]);
                }
            }
        }
        if (c < 2) { issue(c + 2, c + 2 == 2 ? 2 : 0); CPC; }
    }

    int q = lane >> 2;
    int c2 = (lane & 3) * 2;
#pragma unroll
    for (int mt = 0; mt < 2; mt++) {
#pragma unroll
        for (int nt = 0; nt < 8; nt++) {
            float* a = acc[mt * 8 + nt];
            int coln = wn * 64 + nt * 8 + c2;
            int col = col0 + coln;
            float2 bb = *(float2*)(sBias + coln);
#pragma unroll
            for (int h = 0; h < 2; h++) {
                int rr = row0 + wm * 32 + mt * 16 + h * 8 + q;
                if (rr < NN)
                    *(float2*)(g_hn + (size_t)rr * 256 + col) =
                        make_float2(a[2 * h + 0] + bb.x, a[2 * h + 1] + bb.y);
            }
        }
    }
}

// ---------------- scores: zhi @ paw1 (bf16 2-term) -> tanh -> dot paw2 -------
__global__ void __launch_bounds__(256, 2) node_mma2(const float* __restrict__ pab1,
                                                    const float* __restrict__ w2) {
    extern __shared__ char sm[];
    uint32_t sbase = smem_u32(sm);
    float* sBias = (float*)(sm + 98304);
    float* sW2 = (float*)(sm + 98304 + 512);

    int tid = threadIdx.x, lane = tid & 31, wid = tid >> 5;
    int wm = wid & 3, wn = wid >> 2;
    int col0 = blockIdx.x * 128, row0 = blockIdx.y * 128;

    if (tid < 128) { sBias[tid] = pab1[col0 + tid]; sW2[tid] = w2[col0 + tid]; }

    const uint4* A4 = (const uint4*)g_zhi + (size_t)row0 * 32;
    const uint4* Bh4 = (const uint4*)g_pahi + (size_t)col0 * 32;
    const uint4* Bl4 = (const uint4*)g_palo + (size_t)col0 * 32;

    float acc[16][4];
#pragma unroll
    for (int i = 0; i < 16; i++) { acc[i][0] = 0.f; acc[i][1] = 0.f; acc[i][2] = 0.f; acc[i][3] = 0.f; }

    auto issue = [&](int c, int s) {
        uint32_t sa = sbase + s * 49152;
#pragma unroll
        for (int i = 0; i < 4; i++) {
            int elem = tid + 256 * i;
            int r = elem >> 3, u = elem & 7;
            uint32_t o = swz((uint32_t)(r * 128 + u * 16));
            CPA16(sa + o,         A4  + (size_t)r * 32 + c * 8 + u);
            CPA16(sa + 16384 + o, Bh4 + (size_t)r * 32 + c * 8 + u);
            CPA16(sa + 32768 + o, Bl4 + (size_t)r * 32 + c * 8 + u);
        }
    };

    issue(0, 0); CPC;
    issue(1, 1); CPC;

#pragma unroll
    for (int c = 0; c < 4; c++) {
        if (c < 3) { CPW1; } else { CPW0; }
        __syncthreads();
        uint32_t sa = sbase + (c & 1) * 49152;
#pragma unroll
        for (int ks = 0; ks < 4; ks++) {
            uint32_t a0[4], a1[4];
            int kb = ks * 32 + ((lane >> 4) << 4);
            LDSM4(a0, sa + swz((uint32_t)((wm * 32 + (lane & 15)) * 128 + kb)));
            LDSM4(a1, sa + swz((uint32_t)((wm * 32 + 16 + (lane & 15)) * 128 + kb)));
#pragma unroll
            for (int np = 0; np < 4; np++) {
                int g = lane >> 3, li = lane & 7;
                int brow = wn * 64 + np * 16 + ((g >> 1) << 3) + li;
                int bkb = ks * 32 + ((g & 1) << 4);
                uint32_t bh[4], bl[4];
                LDSM4(bh, sa + 16384 + swz((uint32_t)(brow * 128 + bkb)));
                LDSM4(bl, sa + 32768 + swz((uint32_t)(brow * 128 + bkb)));
#pragma unroll
                for (int t = 0; t < 2; t++) {
                    mma_bf16(acc[0 * 8 + np * 2 + t], a0, bh[2 * t], bh[2 * t + 1]);
                    mma_bf16(acc[0 * 8 + np * 2 + t], a0, bl[2 * t], bl[2 * t + 1]);
                    mma_bf16(acc[1 * 8 + np * 2 + t], a1, bh[2 * t], bh[2 * t + 1]);
                    mma_bf16(acc[1 * 8 + np * 2 + t], a1, bl[2 * t], bl[2 * t + 1]);
                }
            }
        }
        if (c < 2) { __syncthreads(); issue(c + 2, c & 1); CPC; }
    }

    int q = lane >> 2;
    int c2 = (lane & 3) * 2;
#pragma unroll
    for (int mt = 0; mt < 2; mt++) {
#pragma unroll
        for (int h = 0; h < 2; h++) {
            int rr = row0 + wm * 32 + mt * 16 + h * 8 + q;
            float part = 0.f;
#pragma unroll
            for (int nt = 0; nt < 8; nt++) {
                float* a = acc[mt * 8 + nt];
                int coln = wn * 64 + nt * 8 + c2;
                part += tanhf(a[2 * h + 0] + sBias[coln])     * sW2[coln];
                part += tanhf(a[2 * h + 1] + sBias[coln + 1]) * sW2[coln + 1];
            }
            part += __shfl_xor_sync(~0u, part, 1);
            part += __shfl_xor_sync(~0u, part, 2);
            if ((lane & 3) == 0 && rr < NN) atomicAdd(&g_scores[rr], part);
        }
    }
}

// ---------------- LayerNorm + residual silu update; z = h_next; bf16 h -------
__global__ void ln_update(int l, const float* __restrict__ lng, const float* __restrict__ lnb) {
    int warp = threadIdx.x >> 5, lane = threadIdx.x & 31;
    int n = blockIdx.x * 8 + warp;
    const float* g = lng + l * 256;
    const float* b = lnb + l * 256;
    const float* row = g_hn + (size_t)n * 256;
    float v[8];
    float s = 0.f, ss = 0.f;
#pragma unroll
    for (int t = 0; t < 8; t++) {
        v[t] = row[lane + 32 * t];
        s += v[t]; ss += v[t] * v[t];
    }
#pragma unroll
    for (int o = 16; o > 0; o >>= 1) {
        s += __shfl_xor_sync(~0u, s, o);
        ss += __shfl_xor_sync(~0u, ss, o);
    }
    float m = s * (1.f / 256.f);
    float var = ss * (1.f / 256.f) - m * m;
    float r = rsqrtf(var + 1e-5f);
    float* hrow = g_h + (size_t)n * 256;
    float* zrow = g_z + (size_t)n * 256;
#pragma unroll
    for (int t = 0; t < 8; t++) {
        int cidx = lane + 32 * t;
        float u = (v[t] - m) * r * g[cidx] + b[cidx];
        float nh = hrow[cidx] + siluf(u);
        hrow[cidx] = nh;
        zrow[cidx] = nh;
        if (l == LL - 1) g_zhi[(size_t)n * 256 + cidx] = __float2bfloat16(nh);
    }
}

// ---------------- per-graph softmax + renormalized attention -----------------
// Global softmax + per-graph renorm == per-graph softmax (global Z cancels;
// the reference's 1e-8 epsilon contributes ~2e-7 relative — negligible).
__global__ void seg_attn() {
    int g = blockIdx.x, t = threadIdx.x;
    int base = g * PG;
    __shared__ float red[256];
    float m = -1e30f;
    for (int i = t; i < PG; i += 256) m = fmaxf(m, g_scores[base + i]);
    red[t] = m;
    __syncthreads();
    for (int o = 128; o > 0; o >>= 1) {
        if (t < o) red[t] = fmaxf(red[t], red[t + o]);
        __syncthreads();
    }
    float gmax = red[0];
    __syncthreads();
    float s = 0.f;
    for (int i = t; i < PG; i += 256) s += expf(g_scores[base + i] - gmax);
    red[t] = s;
    __syncthreads();
    for (int o = 128; o > 0; o >>= 1) {
        if (t < o) red[t] += red[t + o];
        __syncthreads();
    }
    float scale = 1.f / red[0];
    for (int i = t; i < PG; i += 256) g_attn[base + i] = expf(g_scores[base + i] - gmax) * scale;
    g_pooled[g * 256 + t] = 0.f;
}

// ---------------- weighted pooling ------------------------------------------
__global__ void pool_kernel() {
    int g = blockIdx.x, chunk = blockIdx.y, j = threadIdx.x;
    int base = g * PG + chunk * 50;
    float acc = 0.f;
    for (int i = 0; i < 50; i++)
        acc += g_h[(size_t)(base + i) * 256 + j] * g_attn[base + i];
    atomicAdd(&g_pooled[g * 256 + j], acc);
}

// ---------------- head -------------------------------------------------------
__global__ void head_kernel(const float* __restrict__ hw1, const float* __restrict__ hb1,
                            const float* __restrict__ hw2, const float* __restrict__ hb2,
                            float* __restrict__ out) {
    int g = blockIdx.x, j = threadIdx.x;
    __shared__ float ps[256];
    __shared__ float red[256];
    ps[j] = g_pooled[g * 256 + j];
    __syncthreads();
    float acc = hb1[j];
#pragma unroll 8
    for (int k = 0; k < 256; k++) acc += ps[k] * hw1[k * 256 + j];
    red[j] = siluf(acc) * hw2[j];
    __syncthreads();
    for (int o = 128; o > 0; o >>= 1) {
        if (j < o) red[j] += red[j + o];
        __syncthreads();
    }
    if (j == 0) out[g] = red[0] + hb2[0];
}

// ---------------- launch -----------------------------------------------------
extern "C" void kernel_launch(void* const* d_in, const int* in_sizes, int n_in,
                              void* d_out, int out_size) {
    const float* x    = (const float*)d_in[0];
    const float* ea   = (const float*)d_in[1];
    const float* c    = (const float*)d_in[2];
    const int*   eidx = (const int*)  d_in[3];
    const int*   gid  = (const int*)  d_in[4];
    const int*   lid  = (const int*)  d_in[5];
    const float* ew1  = (const float*)d_in[6];
    const float* eb1  = (const float*)d_in[7];
    const float* ew2  = (const float*)d_in[8];
    const float* eb2  = (const float*)d_in[9];
    const float* inw  = (const float*)d_in[10];
    const float* inb  = (const float*)d_in[11];
    const float* lin_w = (const float*)d_in[12];
    const float* lin_b = (const float*)d_in[13];
    const float* cw1  = (const float*)d_in[14];
    const float* cb1  = (const float*)d_in[15];
    const float* cw2  = (const float*)d_in[16];
    const float* cb2  = (const float*)d_in[17];
    const float* lng  = (const float*)d_in[18];
    const float* lnb  = (const float*)d_in[19];
    const float* paw1 = (const float*)d_in[20];
    const float* pab1 = (const float*)d_in[21];
    const float* paw2 = (const float*)d_in[22];
    const float* pab2 = (const float*)d_in[23];
    const float* hw1  = (const float*)d_in[24];
    const float* hb1  = (const float*)d_in[25];
    const float* hw2  = (const float*)d_in[26];
    const float* hb2  = (const float*)d_in[27];
    float* out = (float*)d_out;

    static int attr_done = 0;
    static cudaStream_t s1 = 0;
    static cudaEvent_t evF = 0, evJ = 0;
    if (!attr_done) {
        cudaFuncSetAttribute((const void*)edge_mma,
                             cudaFuncAttributeMaxDynamicSharedMemorySize, PIPE_SMEM);
        cudaFuncSetAttribute((const void*)node0_mma,
                             cudaFuncAttributeMaxDynamicSharedMemorySize, NODE0_SMEM);
        cudaFuncSetAttribute((const void*)node1_mma,
                             cudaFuncAttributeMaxDynamicSharedMemorySize, PIPE_SMEM);
        cudaFuncSetAttribute((const void*)node_mma2,
                             cudaFuncAttributeMaxDynamicSharedMemorySize, PIPE_SMEM);
        cudaStreamCreateWithFlags(&s1, cudaStreamNonBlocking);
        cudaEventCreateWithFlags(&evF, cudaEventDisableTiming);
        cudaEventCreateWithFlags(&evJ, cudaEventDisableTiming);
        attr_done = 1;
    }

    // fork: prep chain (independent of edge sort) runs on s1
    cudaEventRecord(evF, 0);
    cudaStreamWaitEvent(s1, evF, 0);
    prep_W<<<LL * 256, 256, 0, s1>>>(ew2, lin_w);
    prep_bl<<<LL, 256, 0, s1>>>(eb2, lin_w, lin_b);
    prep_nw<<<dim3(8, 8, LL * 2), 256, 0, s1>>>(cw1, cw2);
    prep_pw<<<dim3(8, 8), 256, 0, s1>>>(paw1);
    input_proj<<<NN / 8, 256, 0, s1>>>(x, c, gid, lid, inw, inb);
    cudaEventRecord(evJ, s1);

    // default stream: dst counting sort + R generation
    zero_init<<<(NN + 255) / 256, 256>>>(pab2);
    hist_kernel<<<EE / 256, 256>>>(eidx);
    scan_kernel<<<1, 1024>>>();
    scatter_kernel<<<EE / 256, 256>>>(eidx);
    r_kernel<<<EE / 32, 128>>>(ea, ew1, eb1);

    // join: layer loop needs both chains
    cudaStreamWaitEvent(0, evJ, 0);

    for (int l = 0; l < LL; l++) {
        edge_mma<<<dim3(2, EE / 128), 256, PIPE_SMEM>>>(l);
        node0_mma<<<dim3(2, NPAD / 128), 256, NODE0_SMEM>>>(l, cb1);
        node1_mma<<<dim3(2, NPAD / 128), 256, PIPE_SMEM>>>(l, cb2);
        ln_update<<<NN / 8, 256>>>(l, lng, lnb);
    }

    node_mma2<<<dim3(2, NPAD / 128), 256, PIPE_SMEM>>>(pab1, paw2);
    seg_attn<<<GB, 256>>>();
    pool_kernel<<<dim3(GB, PG / 50), 256>>>();
    head_kernel<<<GB, 256>>>(hw1, hb1, hw2, hb2, out);
    (void)in_sizes; (void)n_in; (void)out_size;
}